// round 10
// baseline (speedup 1.0000x reference)
#include <cuda_runtime.h>
#include <cuda_fp16.h>
#include <cstdint>

// ---------------------------------------------------------------------------
// SpanClassifier via portable mma.sync fp16-split GEMMs.
//   B=8, S=2048, D=256, NREL=129
// Round 10: ntp-paired MMA scheduling. Two B-column groups are loaded
// together, then MMAs issue in phases of 8 independent accumulators, doubling
// same-accumulator reuse separation (4 -> 8) to cover HMMA latency.
//   proj:       3 MMAs (hi*hi + hi*lo + lo*hi)  -> error ~2^-22
//   qr/scores:  2 MMAs (hi*hi + hi_A*lo_B)      -> error ~2^-11
// Mainloop: single-barrier 2-stage cp.async pipeline (R7).
// ---------------------------------------------------------------------------

namespace {
constexpr int B_   = 8;
constexpr int S_   = 2048;
constexpr int D_   = 256;
constexpr int NREL = 129;
constexpr int QRS  = 132;
constexpr int BS_  = B_ * S_;   // 16384

constexpr int KC    = 32;                 // k-chunk (fp16 elems)
constexpr int NCH   = D_ / KC;            // 8
constexpr int STRB  = 80;                 // smem row stride bytes (64 data + 16 pad)
constexpr int TILE_B = 128 * STRB;        // 10240 bytes
constexpr int STAGE_B = 4 * TILE_B;       // 40960 bytes (AHI,ALO,BHI,BLO)
constexpr int SMEM_DYN = 2 * STAGE_B;     // 81920 bytes
constexpr int T_AHI = 0;
constexpr int T_ALO = TILE_B;
constexpr int T_BHI = 2 * TILE_B;
constexpr int T_BLO = 3 * TILE_B;
}

// ---------------- scratch (device globals; no runtime allocation) ----------
__device__ __half g_Xhi[BS_ * D_];
__device__ __half g_Xlo[BS_ * D_];
__device__ __half g_Phi[4][BS_ * D_];
__device__ __half g_Plo[4][BS_ * D_];
__device__ __half g_Whi[4][D_ * D_];
__device__ __half g_Wlo[4][D_ * D_];
__device__ __half g_Rhi[2][NREL * D_];
__device__ __half g_Rlo[2][NREL * D_];
__device__ float g_QR[2][BS_ * QRS];

// ---------------- PTX helpers ----------------------------------------------
__device__ __forceinline__ uint32_t smem_u32(const void* p) {
    uint32_t a;
    asm("{ .reg .u64 t; cvta.to.shared.u64 t, %1; cvt.u32.u64 %0, t; }"
        : "=r"(a) : "l"(p));
    return a;
}

#define LDSM4(R, addr)                                                        \
    asm volatile("ldmatrix.sync.aligned.m8n8.x4.shared.b16 {%0,%1,%2,%3}, [%4];" \
                 : "=r"((R)[0]), "=r"((R)[1]), "=r"((R)[2]), "=r"((R)[3])     \
                 : "r"(addr))

#define MMA_F16(C, A, B0, B1)                                                 \
    asm volatile("mma.sync.aligned.m16n8k16.row.col.f32.f16.f16.f32 "         \
                 "{%0,%1,%2,%3},{%4,%5,%6,%7},{%8,%9},{%0,%1,%2,%3};"         \
                 : "+f"((C)[0]), "+f"((C)[1]), "+f"((C)[2]), "+f"((C)[3])     \
                 : "r"((A)[0]), "r"((A)[1]), "r"((A)[2]), "r"((A)[3]),        \
                   "r"(B0), "r"(B1))

__device__ __forceinline__ void cp16(uint32_t dst, const void* src, bool valid) {
    uint32_t n = valid ? 16u : 0u;
    asm volatile("cp.async.cg.shared.global [%0], [%1], 16, %2;"
                 :: "r"(dst), "l"(src), "r"(n));
}
#define CP_COMMIT() asm volatile("cp.async.commit_group;" ::: "memory")
#define CP_WAIT0()  asm volatile("cp.async.wait_group 0;" ::: "memory")

// ---------------- stage prefetch ---------------------------------------------
// THREE=true loads AHI/ALO/BHI/BLO; THREE=false skips ALO.
template <bool THREE>
__device__ __forceinline__ void prefetch_stage(
    uint32_t smstage,
    const __half* __restrict__ Ahi, const __half* __restrict__ Alo,
    const __half* __restrict__ Bhi, const __half* __restrict__ Blo,
    int rowA0, int rowB0, int bLim, int col0, int tid)
{
#pragma unroll
    for (int t = 0; t < 2; t++) {
        const int idx = t * 256 + tid;     // 0..511
        const int r   = idx >> 2;          // 0..127
        const int c4  = idx & 3;           // 16B group
        const uint32_t so = (uint32_t)(r * STRB + c4 * 16);
        const size_t gao = (size_t)(rowA0 + r) * D_ + col0 + c4 * 8;
        cp16(smstage + T_AHI + so, Ahi + gao, true);
        if (THREE)
            cp16(smstage + T_ALO + so, Alo + gao, true);
        const bool bv = (rowB0 + r) < bLim;
        const int gbr = bv ? (rowB0 + r) : 0;
        const size_t gbo = (size_t)gbr * D_ + col0 + c4 * 8;
        cp16(smstage + T_BHI + so, Bhi + gbo, bv);
        cp16(smstage + T_BLO + so, Blo + gbo, bv);
    }
}

// ---------------- GEMM core: acc[2][8][4] = A[128,256] * B^T -----------------
// Warp grid 4x2 (m x n): warp computes 32x64 via 2x8 m16n8k16 tiles.
// ntp-paired phases: 8 independent MMAs per phase.
extern __shared__ char dynsm[];

template <bool THREE>
__device__ __forceinline__ void gemm_mma(
    const __half* __restrict__ Ahi, const __half* __restrict__ Alo,
    const __half* __restrict__ Bhi, const __half* __restrict__ Blo,
    int rowA0, int rowB0, int bLim, float acc[2][8][4])
{
    const int tid  = threadIdx.x;
    const int lane = tid & 31;
    const int wid  = tid >> 5;
    const int mw   = wid >> 1;   // 0..3
    const int nw   = wid & 1;    // 0..1

    const uint32_t smb = smem_u32(dynsm);

    const int lrow       = lane & 15;
    const uint32_t khalf = (uint32_t)((lane >> 4) * 16);

    const uint32_t aOff = (uint32_t)((mw * 32 + lrow) * STRB) + khalf;
    const uint32_t bOff = (uint32_t)((nw * 64 + lrow) * STRB) + khalf;

#pragma unroll
    for (int mt = 0; mt < 2; mt++)
#pragma unroll
        for (int nt = 0; nt < 8; nt++)
#pragma unroll
            for (int e = 0; e < 4; e++) acc[mt][nt][e] = 0.f;

    prefetch_stage<THREE>(smb, Ahi, Alo, Bhi, Blo, rowA0, rowB0, bLim, 0, tid);
    CP_COMMIT();

    for (int c = 0; c < NCH; c++) {
        CP_WAIT0();
        __syncthreads();   // publishes chunk c; guards stage reuse

        if (c + 1 < NCH) {
            prefetch_stage<THREE>(smb + ((c + 1) & 1) * STAGE_B, Ahi, Alo,
                                  Bhi, Blo, rowA0, rowB0, bLim,
                                  (c + 1) * KC, tid);
            CP_COMMIT();
        }

        const uint32_t st = smb + (c & 1) * STAGE_B;
        const uint32_t aHi = st + T_AHI + aOff;
        const uint32_t bHi = st + T_BHI + bOff;

#pragma unroll
        for (int ks = 0; ks < 2; ks++) {
            const uint32_t ko = (uint32_t)(ks * 32);
            uint32_t ah[2][4], al[2][4];
#pragma unroll
            for (int mt = 0; mt < 2; mt++) {
                LDSM4(ah[mt], aHi + (uint32_t)(mt * 16 * STRB) + ko);
                if (THREE)
                    LDSM4(al[mt], aHi + (uint32_t)(TILE_B + mt * 16 * STRB) + ko);
            }
#pragma unroll
            for (int p = 0; p < 2; p++) {
                // Load B fragments for ntp = 2p and 2p+1 together.
                uint32_t bh[2][4], bl[2][4];
#pragma unroll
                for (int u = 0; u < 2; u++) {
                    const uint32_t nb =
                        (uint32_t)((2 * p + u) * 16 * STRB) + ko;
                    LDSM4(bh[u], bHi + nb);
                    LDSM4(bl[u], bHi + (uint32_t)TILE_B + nb);
                }
                const int n0 = 4 * p;
                // hh phase: 8 independent MMAs (8 distinct accumulators)
                MMA_F16(acc[0][n0 + 0], ah[0], bh[0][0], bh[0][2]);
                MMA_F16(acc[1][n0 + 0], ah[1], bh[0][0], bh[0][2]);
                MMA_F16(acc[0][n0 + 1], ah[0], bh[0][1], bh[0][3]);
                MMA_F16(acc[1][n0 + 1], ah[1], bh[0][1], bh[0][3]);
                MMA_F16(acc[0][n0 + 2], ah[0], bh[1][0], bh[1][2]);
                MMA_F16(acc[1][n0 + 2], ah[1], bh[1][0], bh[1][2]);
                MMA_F16(acc[0][n0 + 3], ah[0], bh[1][1], bh[1][3]);
                MMA_F16(acc[1][n0 + 3], ah[1], bh[1][1], bh[1][3]);
                // hl phase: same 8 accumulators, reuse separation = 8
                MMA_F16(acc[0][n0 + 0], ah[0], bl[0][0], bl[0][2]);
                MMA_F16(acc[1][n0 + 0], ah[1], bl[0][0], bl[0][2]);
                MMA_F16(acc[0][n0 + 1], ah[0], bl[0][1], bl[0][3]);
                MMA_F16(acc[1][n0 + 1], ah[1], bl[0][1], bl[0][3]);
                MMA_F16(acc[0][n0 + 2], ah[0], bl[1][0], bl[1][2]);
                MMA_F16(acc[1][n0 + 2], ah[1], bl[1][0], bl[1][2]);
                MMA_F16(acc[0][n0 + 3], ah[0], bl[1][1], bl[1][3]);
                MMA_F16(acc[1][n0 + 3], ah[1], bl[1][1], bl[1][3]);
                if (THREE) {
                    // lh phase (proj only)
                    MMA_F16(acc[0][n0 + 0], al[0], bh[0][0], bh[0][2]);
                    MMA_F16(acc[1][n0 + 0], al[1], bh[0][0], bh[0][2]);
                    MMA_F16(acc[0][n0 + 1], al[0], bh[0][1], bh[0][3]);
                    MMA_F16(acc[1][n0 + 1], al[1], bh[0][1], bh[0][3]);
                    MMA_F16(acc[0][n0 + 2], al[0], bh[1][0], bh[1][2]);
                    MMA_F16(acc[1][n0 + 2], al[1], bh[1][0], bh[1][2]);
                    MMA_F16(acc[0][n0 + 3], al[0], bh[1][1], bh[1][3]);
                    MMA_F16(acc[1][n0 + 3], al[1], bh[1][1], bh[1][3]);
                }
            }
        }
    }
}

// Fragment -> (row, col): row = mw*32 + mt*16 + (lane>>2) + 8*h ;
// col = nw*64 + nt*8 + (lane&3)*2 + {0,1} ; acc element e = h*2 + {0,1}.

// ---------------- 0) converts -------------------------------------------------
__device__ __forceinline__ void split_store(float x, __half* hi,
                                            __half* lo, size_t i)
{
    __half h = __float2half_rn(x);
    hi[i] = h;
    lo[i] = __float2half_rn(x - __half2float(h));
}

__global__ void convert_x_kernel(const float* __restrict__ src) {
    const int i4 = blockIdx.x * 256 + threadIdx.x;
    const size_t i = (size_t)i4 * 4;
    if (i + 3 < (size_t)BS_ * D_) {
        float4 v = *(const float4*)(src + i);
        __half h0 = __float2half_rn(v.x), h1 = __float2half_rn(v.y);
        __half h2 = __float2half_rn(v.z), h3 = __float2half_rn(v.w);
        __half2 hp0 = __halves2half2(h0, h1), hp1 = __halves2half2(h2, h3);
        __half2 lp0 = __halves2half2(__float2half_rn(v.x - __half2float(h0)),
                                     __float2half_rn(v.y - __half2float(h1)));
        __half2 lp1 = __halves2half2(__float2half_rn(v.z - __half2float(h2)),
                                     __float2half_rn(v.w - __half2float(h3)));
        *(__half2*)(g_Xhi + i)     = hp0;
        *(__half2*)(g_Xhi + i + 2) = hp1;
        *(__half2*)(g_Xlo + i)     = lp0;
        *(__half2*)(g_Xlo + i + 2) = lp1;
    }
}

__global__ void convert_small_kernel(
    const float* __restrict__ w0, const float* __restrict__ w1,
    const float* __restrict__ w2, const float* __restrict__ w3,
    const float* __restrict__ r0, const float* __restrict__ r1)
{
    const int z = blockIdx.y;
    const float* src;
    __half *hi, *lo;
    int n;
    if (z < 4) {
        src = (z == 0) ? w0 : (z == 1) ? w1 : (z == 2) ? w2 : w3;
        hi = g_Whi[z]; lo = g_Wlo[z]; n = D_ * D_;
    } else {
        src = (z == 4) ? r0 : r1;
        hi = g_Rhi[z - 4]; lo = g_Rlo[z - 4]; n = NREL * D_;
    }
    int i = blockIdx.x * 256 + threadIdx.x;
    if (i < n) split_store(src[i], hi, lo, i);
}

// ---------------- 1) projections (full 3-MMA precision) ----------------------
__global__ void __launch_bounds__(256, 2)
proj_kernel(const float* __restrict__ bq1, const float* __restrict__ bk1,
            const float* __restrict__ bq2, const float* __restrict__ bk2)
{
    const int z = blockIdx.z;
    const float* bias = (z == 0) ? bq1 : (z == 1) ? bk1 : (z == 2) ? bq2 : bk2;
    const float scale = (z == 0 || z == 2) ? 0.0625f : 1.0f;

    const int mBase = blockIdx.y * 128;
    const int nBase = blockIdx.x * 128;

    float acc[2][8][4];
    gemm_mma<true>(g_Xhi, g_Xlo, g_Whi[z], g_Wlo[z], mBase, nBase, 1 << 30, acc);

    const int lane = threadIdx.x & 31, wid = threadIdx.x >> 5;
    const int mw = wid >> 1, nw = wid & 1;

#pragma unroll
    for (int mt = 0; mt < 2; mt++) {
#pragma unroll
        for (int h = 0; h < 2; h++) {
            const int m = mBase + mw * 32 + mt * 16 + (lane >> 2) + 8 * h;
            __half* dhi = g_Phi[z] + (size_t)m * D_;
            __half* dlo = g_Plo[z] + (size_t)m * D_;
#pragma unroll
            for (int nt = 0; nt < 8; nt++) {
                const int col = nBase + nw * 64 + nt * 8 + (lane & 3) * 2;
                float y0 = (acc[mt][nt][h * 2 + 0] + bias[col + 0]) * scale;
                float y1 = (acc[mt][nt][h * 2 + 1] + bias[col + 1]) * scale;
                __half h0 = __float2half_rn(y0);
                __half h1 = __float2half_rn(y1);
                __half2 hp = __halves2half2(h0, h1);
                __half2 lp = __halves2half2(
                    __float2half_rn(y0 - __half2float(h0)),
                    __float2half_rn(y1 - __half2float(h1)));
                *(__half2*)(dhi + col) = hp;
                *(__half2*)(dlo + col) = lp;
            }
        }
    }
}

// ---------------- 2) q_rel: cols 0..127 via GEMM (2-MMA) ---------------------
__global__ void __launch_bounds__(256, 2)
qr_kernel()
{
    const int head  = blockIdx.z;
    const int mBase = blockIdx.y * 128;

    float acc[2][8][4];
    gemm_mma<false>(g_Phi[head * 2], g_Plo[head * 2], g_Rhi[head], g_Rlo[head],
                    mBase, 0, 128, acc);

    const int lane = threadIdx.x & 31, wid = threadIdx.x >> 5;
    const int mw = wid >> 1, nw = wid & 1;

#pragma unroll
    for (int mt = 0; mt < 2; mt++) {
#pragma unroll
        for (int h = 0; h < 2; h++) {
            const int m = mBase + mw * 32 + mt * 16 + (lane >> 2) + 8 * h;
            float* dst = g_QR[head] + (size_t)m * QRS;
#pragma unroll
            for (int nt = 0; nt < 8; nt++) {
                const int col = nw * 64 + nt * 8 + (lane & 3) * 2;
                *(float2*)(dst + col) =
                    make_float2(acc[mt][nt][h * 2 + 0], acc[mt][nt][h * 2 + 1]);
            }
        }
    }
}

// ---------------- 2b) q_rel column 128 (rel position +64) via GEMV -----------
__global__ void __launch_bounds__(256)
qr_col_kernel()
{
    const int gw   = blockIdx.x * 8 + (threadIdx.x >> 5);  // 0..2047
    const int lane = threadIdx.x & 31;
    const int head = gw >> 10;
    const int row0 = (gw & 1023) * 16;

    float rf[8];
    {
        const __half* rh = g_Rhi[head] + (size_t)128 * D_ + lane * 8;
        const __half* rl = g_Rlo[head] + (size_t)128 * D_ + lane * 8;
        uint4 vh = *(const uint4*)rh;
        uint4 vl = *(const uint4*)rl;
        const __half* ph = (const __half*)&vh;
        const __half* pl = (const __half*)&vl;
#pragma unroll
        for (int j = 0; j < 8; j++)
            rf[j] = __half2float(ph[j]) + __half2float(pl[j]);
    }

    const __half* Qhi = g_Phi[head * 2];
    const __half* Qlo = g_Plo[head * 2];

    for (int r = 0; r < 16; r++) {
        const int row = row0 + r;
        uint4 vh = *(const uint4*)(Qhi + (size_t)row * D_ + lane * 8);
        uint4 vl = *(const uint4*)(Qlo + (size_t)row * D_ + lane * 8);
        const __half* ph = (const __half*)&vh;
        const __half* pl = (const __half*)&vl;
        float s = 0.f;
#pragma unroll
        for (int j = 0; j < 8; j++)
            s += (__half2float(ph[j]) + __half2float(pl[j])) * rf[j];
#pragma unroll
        for (int o = 16; o > 0; o >>= 1)
            s += __shfl_xor_sync(0xFFFFFFFF, s, o);
        if (lane == 0) g_QR[head][(size_t)row * QRS + 128] = s;
    }
}

// ---------------- 3) scores (2-MMA) ------------------------------------------
__global__ void __launch_bounds__(256, 2)
scores_kernel(const int* __restrict__ mask, float* __restrict__ out)
{
    const int z    = blockIdx.z;
    const int head = z >> 3;
    const int b    = z & 7;
    const int qBase = blockIdx.y * 128;
    const int kBase = blockIdx.x * 128;

    const size_t po = (size_t)b * S_ * D_;
    float acc[2][8][4];
    gemm_mma<false>(g_Phi[head * 2 + 0] + po, g_Plo[head * 2 + 0] + po,
                    g_Phi[head * 2 + 1] + po, g_Plo[head * 2 + 1] + po,
                    qBase, kBase, 1 << 30, acc);

    const int lane = threadIdx.x & 31, wid = threadIdx.x >> 5;
    const int mw = wid >> 1, nw = wid & 1;
    const int* mrow = mask + b * S_;

#pragma unroll
    for (int mt = 0; mt < 2; mt++) {
#pragma unroll
        for (int h = 0; h < 2; h++) {
            const int qg = qBase + mw * 32 + mt * 16 + (lane >> 2) + 8 * h;
            const int mq = mrow[qg];
            const float* qr = g_QR[head] + ((size_t)b * S_ + qg) * QRS;
            float* orow = out + (((size_t)head * B_ + b) * S_ + qg) * S_;
#pragma unroll
            for (int nt = 0; nt < 8; nt++) {
                const int kg = kBase + nw * 64 + nt * 8 + (lane & 3) * 2;
                int d0 = kg - qg;
                int d1 = d0 + 1;
                d0 = (d0 < -64) ? -64 : ((d0 > 64) ? 64 : d0);
                d1 = (d1 < -64) ? -64 : ((d1 > 64) ? 64 : d1);
                float v0 = acc[mt][nt][h * 2 + 0] + qr[d0 + 64];
                float v1 = acc[mt][nt][h * 2 + 1] + qr[d1 + 64];
                if (mq == 0 || mrow[kg + 0] == 0) v0 = -1e18f;
                if (mq == 0 || mrow[kg + 1] == 0) v1 = -1e18f;
                float2 v = make_float2(v0, v1);
                *(float2*)(orow + kg) = v;
            }
        }
    }
}

// ---------------- launch --------------------------------------------------------
extern "C" void kernel_launch(void* const* d_in, const int* in_sizes, int n_in,
                              void* d_out, int out_size)
{
    const float* repre = (const float*)d_in[0];
    const int*   mask  = (const int*)d_in[1];
    const float* wq1 = (const float*)d_in[2];
    const float* bq1 = (const float*)d_in[3];
    const float* wk1 = (const float*)d_in[4];
    const float* bk1 = (const float*)d_in[5];
    const float* rel1 = (const float*)d_in[6];
    const float* wq2 = (const float*)d_in[7];
    const float* bq2 = (const float*)d_in[8];
    const float* wk2 = (const float*)d_in[9];
    const float* bk2 = (const float*)d_in[10];
    const float* rel2 = (const float*)d_in[11];
    float* out = (float*)d_out;
    (void)in_sizes; (void)n_in; (void)out_size;

    cudaFuncSetAttribute(proj_kernel,
                         cudaFuncAttributeMaxDynamicSharedMemorySize, SMEM_DYN);
    cudaFuncSetAttribute(qr_kernel,
                         cudaFuncAttributeMaxDynamicSharedMemorySize, SMEM_DYN);
    cudaFuncSetAttribute(scores_kernel,
                         cudaFuncAttributeMaxDynamicSharedMemorySize, SMEM_DYN);

    const int NX4 = BS_ * D_ / 4;
    const int NW = D_ * D_;

    convert_x_kernel<<<(NX4 + 255) / 256, 256>>>(repre);
    convert_small_kernel<<<dim3((NW + 255) / 256, 6), 256>>>(
        wq1, wk1, wq2, wk2, rel1, rel2);

    proj_kernel<<<dim3(2, 128, 4), 256, SMEM_DYN>>>(bq1, bk1, bq2, bk2);
    qr_kernel<<<dim3(1, 128, 2), 256, SMEM_DYN>>>();
    qr_col_kernel<<<256, 256>>>();
    scores_kernel<<<dim3(16, 16, 16), 256, SMEM_DYN>>>(mask, out);
}

// round 11
// speedup vs baseline: 1.0667x; 1.0667x over previous
#include <cuda_runtime.h>
#include <cuda_fp16.h>
#include <cstdint>

// ---------------------------------------------------------------------------
// SpanClassifier via portable mma.sync fp16-split GEMMs.
//   B=8, S=2048, D=256, NREL=129
// Round 11: scores/qr move to 512-thread CTAs with 4x4 warp grid and 32x32
// warp tiles (acc 32 regs/thread, <=64 total) -> 32 warps/SM, double the
// latency-hiding of the previous 256-thr/32x64 config. 3-tile cp.async stages
// (A-hi, B-hi, B-lo). Proj keeps the 3-MMA 256-thr core for full precision.
//   proj:       3 MMAs (hi*hi + hi*lo + lo*hi)  -> error ~2^-22
//   qr/scores:  2 MMAs (hi*hi + hi_A*lo_B)      -> error ~2^-11
// ---------------------------------------------------------------------------

namespace {
constexpr int B_   = 8;
constexpr int S_   = 2048;
constexpr int D_   = 256;
constexpr int NREL = 129;
constexpr int QRS  = 132;
constexpr int BS_  = B_ * S_;   // 16384

constexpr int KC    = 32;                 // k-chunk (fp16 elems)
constexpr int NCH   = D_ / KC;            // 8
constexpr int STRB  = 80;                 // smem row stride bytes (64 data + 16 pad)
constexpr int TILE_B = 128 * STRB;        // 10240 bytes

// proj (3-MMA) staging: 4 tiles
constexpr int T_AHI = 0;
constexpr int T_ALO = TILE_B;
constexpr int T_BHI = 2 * TILE_B;
constexpr int T_BLO = 3 * TILE_B;
constexpr int STAGE4_B = 4 * TILE_B;      // 40960
constexpr int SMEM4 = 2 * STAGE4_B;       // 81920

// scores/qr (2-MMA) staging: 3 tiles
constexpr int T2_A  = 0;
constexpr int T2_BH = TILE_B;
constexpr int T2_BL = 2 * TILE_B;
constexpr int STAGE3_B = 3 * TILE_B;      // 30720
constexpr int SMEM3 = 2 * STAGE3_B;       // 61440
}

// ---------------- scratch (device globals; no runtime allocation) ----------
__device__ __half g_Xhi[BS_ * D_];
__device__ __half g_Xlo[BS_ * D_];
__device__ __half g_Phi[4][BS_ * D_];
__device__ __half g_Plo[4][BS_ * D_];
__device__ __half g_Whi[4][D_ * D_];
__device__ __half g_Wlo[4][D_ * D_];
__device__ __half g_Rhi[2][NREL * D_];
__device__ __half g_Rlo[2][NREL * D_];
__device__ float g_QR[2][BS_ * QRS];

// ---------------- PTX helpers ----------------------------------------------
__device__ __forceinline__ uint32_t smem_u32(const void* p) {
    uint32_t a;
    asm("{ .reg .u64 t; cvta.to.shared.u64 t, %1; cvt.u32.u64 %0, t; }"
        : "=r"(a) : "l"(p));
    return a;
}

#define LDSM4(R, addr)                                                        \
    asm volatile("ldmatrix.sync.aligned.m8n8.x4.shared.b16 {%0,%1,%2,%3}, [%4];" \
                 : "=r"((R)[0]), "=r"((R)[1]), "=r"((R)[2]), "=r"((R)[3])     \
                 : "r"(addr))

#define MMA_F16(C, A, B0, B1)                                                 \
    asm volatile("mma.sync.aligned.m16n8k16.row.col.f32.f16.f16.f32 "         \
                 "{%0,%1,%2,%3},{%4,%5,%6,%7},{%8,%9},{%0,%1,%2,%3};"         \
                 : "+f"((C)[0]), "+f"((C)[1]), "+f"((C)[2]), "+f"((C)[3])     \
                 : "r"((A)[0]), "r"((A)[1]), "r"((A)[2]), "r"((A)[3]),        \
                   "r"(B0), "r"(B1))

__device__ __forceinline__ void cp16(uint32_t dst, const void* src, bool valid) {
    uint32_t n = valid ? 16u : 0u;
    asm volatile("cp.async.cg.shared.global [%0], [%1], 16, %2;"
                 :: "r"(dst), "l"(src), "r"(n));
}
#define CP_COMMIT() asm volatile("cp.async.commit_group;" ::: "memory")
#define CP_WAIT0()  asm volatile("cp.async.wait_group 0;" ::: "memory")

extern __shared__ char dynsm[];

// ============================================================================
//  (A) 3-MMA core for proj: 256 threads, 4x2 warp grid, 32x64 warp tiles
// ============================================================================
__device__ __forceinline__ void prefetch4(
    uint32_t smstage,
    const __half* __restrict__ Ahi, const __half* __restrict__ Alo,
    const __half* __restrict__ Bhi, const __half* __restrict__ Blo,
    int rowA0, int rowB0, int col0, int tid)
{
#pragma unroll
    for (int t = 0; t < 2; t++) {
        const int idx = t * 256 + tid;     // 0..511
        const int r   = idx >> 2;
        const int c4  = idx & 3;
        const uint32_t so = (uint32_t)(r * STRB + c4 * 16);
        const size_t gao = (size_t)(rowA0 + r) * D_ + col0 + c4 * 8;
        cp16(smstage + T_AHI + so, Ahi + gao, true);
        cp16(smstage + T_ALO + so, Alo + gao, true);
        const size_t gbo = (size_t)(rowB0 + r) * D_ + col0 + c4 * 8;
        cp16(smstage + T_BHI + so, Bhi + gbo, true);
        cp16(smstage + T_BLO + so, Blo + gbo, true);
    }
}

__device__ __forceinline__ void gemm_mma3(
    const __half* __restrict__ Ahi, const __half* __restrict__ Alo,
    const __half* __restrict__ Bhi, const __half* __restrict__ Blo,
    int rowA0, int rowB0, float acc[2][8][4])
{
    const int tid  = threadIdx.x;
    const int lane = tid & 31;
    const int wid  = tid >> 5;
    const int mw   = wid >> 1;   // 0..3
    const int nw   = wid & 1;    // 0..1

    const uint32_t smb = smem_u32(dynsm);
    const int lrow       = lane & 15;
    const uint32_t khalf = (uint32_t)((lane >> 4) * 16);
    const uint32_t aOff = (uint32_t)((mw * 32 + lrow) * STRB) + khalf;
    const uint32_t bOff = (uint32_t)((nw * 64 + lrow) * STRB) + khalf;

#pragma unroll
    for (int mt = 0; mt < 2; mt++)
#pragma unroll
        for (int nt = 0; nt < 8; nt++)
#pragma unroll
            for (int e = 0; e < 4; e++) acc[mt][nt][e] = 0.f;

    prefetch4(smb, Ahi, Alo, Bhi, Blo, rowA0, rowB0, 0, tid);
    CP_COMMIT();

    for (int c = 0; c < NCH; c++) {
        CP_WAIT0();
        __syncthreads();
        if (c + 1 < NCH) {
            prefetch4(smb + ((c + 1) & 1) * STAGE4_B, Ahi, Alo, Bhi, Blo,
                      rowA0, rowB0, (c + 1) * KC, tid);
            CP_COMMIT();
        }
        const uint32_t st = smb + (c & 1) * STAGE4_B;
        const uint32_t aHi = st + T_AHI + aOff;
        const uint32_t bHi = st + T_BHI + bOff;

#pragma unroll
        for (int ks = 0; ks < 2; ks++) {
            const uint32_t ko = (uint32_t)(ks * 32);
            uint32_t ah[2][4], al[2][4];
#pragma unroll
            for (int mt = 0; mt < 2; mt++) {
                LDSM4(ah[mt], aHi + (uint32_t)(mt * 16 * STRB) + ko);
                LDSM4(al[mt], aHi + (uint32_t)(TILE_B + mt * 16 * STRB) + ko);
            }
#pragma unroll
            for (int p = 0; p < 2; p++) {
                uint32_t bh[2][4], bl[2][4];
#pragma unroll
                for (int u = 0; u < 2; u++) {
                    const uint32_t nb = (uint32_t)((2 * p + u) * 16 * STRB) + ko;
                    LDSM4(bh[u], bHi + nb);
                    LDSM4(bl[u], bHi + (uint32_t)TILE_B + nb);
                }
                const int n0 = 4 * p;
                MMA_F16(acc[0][n0 + 0], ah[0], bh[0][0], bh[0][2]);
                MMA_F16(acc[1][n0 + 0], ah[1], bh[0][0], bh[0][2]);
                MMA_F16(acc[0][n0 + 1], ah[0], bh[0][1], bh[0][3]);
                MMA_F16(acc[1][n0 + 1], ah[1], bh[0][1], bh[0][3]);
                MMA_F16(acc[0][n0 + 2], ah[0], bh[1][0], bh[1][2]);
                MMA_F16(acc[1][n0 + 2], ah[1], bh[1][0], bh[1][2]);
                MMA_F16(acc[0][n0 + 3], ah[0], bh[1][1], bh[1][3]);
                MMA_F16(acc[1][n0 + 3], ah[1], bh[1][1], bh[1][3]);
                MMA_F16(acc[0][n0 + 0], ah[0], bl[0][0], bl[0][2]);
                MMA_F16(acc[1][n0 + 0], ah[1], bl[0][0], bl[0][2]);
                MMA_F16(acc[0][n0 + 1], ah[0], bl[0][1], bl[0][3]);
                MMA_F16(acc[1][n0 + 1], ah[1], bl[0][1], bl[0][3]);
                MMA_F16(acc[0][n0 + 2], ah[0], bl[1][0], bl[1][2]);
                MMA_F16(acc[1][n0 + 2], ah[1], bl[1][0], bl[1][2]);
                MMA_F16(acc[0][n0 + 3], ah[0], bl[1][1], bl[1][3]);
                MMA_F16(acc[1][n0 + 3], ah[1], bl[1][1], bl[1][3]);
                MMA_F16(acc[0][n0 + 0], al[0], bh[0][0], bh[0][2]);
                MMA_F16(acc[1][n0 + 0], al[1], bh[0][0], bh[0][2]);
                MMA_F16(acc[0][n0 + 1], al[0], bh[0][1], bh[0][3]);
                MMA_F16(acc[1][n0 + 1], al[1], bh[0][1], bh[0][3]);
                MMA_F16(acc[0][n0 + 2], al[0], bh[1][0], bh[1][2]);
                MMA_F16(acc[1][n0 + 2], al[1], bh[1][0], bh[1][2]);
                MMA_F16(acc[0][n0 + 3], al[0], bh[1][1], bh[1][3]);
                MMA_F16(acc[1][n0 + 3], al[1], bh[1][1], bh[1][3]);
            }
        }
    }
}

// ============================================================================
//  (B) 2-MMA core for scores/qr: 512 threads, 4x4 warp grid, 32x32 warp tiles
// ============================================================================
__device__ __forceinline__ void prefetch3(
    uint32_t smstage,
    const __half* __restrict__ Ahi,
    const __half* __restrict__ Bhi, const __half* __restrict__ Blo,
    int rowA0, int rowB0, int bLim, int col0, int tid)
{
    const int r  = tid >> 2;          // 0..127
    const int c4 = tid & 3;
    const uint32_t so = (uint32_t)(r * STRB + c4 * 16);
    const size_t gao = (size_t)(rowA0 + r) * D_ + col0 + c4 * 8;
    cp16(smstage + T2_A + so, Ahi + gao, true);
    const bool bv = (rowB0 + r) < bLim;
    const int gbr = bv ? (rowB0 + r) : 0;
    const size_t gbo = (size_t)gbr * D_ + col0 + c4 * 8;
    cp16(smstage + T2_BH + so, Bhi + gbo, bv);
    cp16(smstage + T2_BL + so, Blo + gbo, bv);
}

__device__ __forceinline__ void gemm_mma2(
    const __half* __restrict__ Ahi,
    const __half* __restrict__ Bhi, const __half* __restrict__ Blo,
    int rowA0, int rowB0, int bLim, float acc[2][4][4])
{
    const int tid  = threadIdx.x;
    const int lane = tid & 31;
    const int wid  = tid >> 5;       // 0..15
    const int mw   = wid >> 2;       // 0..3
    const int nwq  = wid & 3;        // 0..3

    const uint32_t smb = smem_u32(dynsm);
    const int lrow       = lane & 15;
    const uint32_t khalf = (uint32_t)((lane >> 4) * 16);
    const uint32_t aOff = (uint32_t)((mw * 32 + lrow) * STRB) + khalf;
    const uint32_t bOff = (uint32_t)((nwq * 32 + lrow) * STRB) + khalf;

#pragma unroll
    for (int mt = 0; mt < 2; mt++)
#pragma unroll
        for (int nt = 0; nt < 4; nt++)
#pragma unroll
            for (int e = 0; e < 4; e++) acc[mt][nt][e] = 0.f;

    prefetch3(smb, Ahi, Bhi, Blo, rowA0, rowB0, bLim, 0, tid);
    CP_COMMIT();

    for (int c = 0; c < NCH; c++) {
        CP_WAIT0();
        __syncthreads();
        if (c + 1 < NCH) {
            prefetch3(smb + ((c + 1) & 1) * STAGE3_B, Ahi, Bhi, Blo,
                      rowA0, rowB0, bLim, (c + 1) * KC, tid);
            CP_COMMIT();
        }
        const uint32_t st = smb + (c & 1) * STAGE3_B;
        const uint32_t aB  = st + T2_A + aOff;
        const uint32_t bhB = st + T2_BH + bOff;

#pragma unroll
        for (int ks = 0; ks < 2; ks++) {
            const uint32_t ko = (uint32_t)(ks * 32);
            uint32_t ah[2][4], bh[2][4], bl[2][4];
            LDSM4(ah[0], aB + ko);
            LDSM4(ah[1], aB + (uint32_t)(16 * STRB) + ko);
            LDSM4(bh[0], bhB + ko);
            LDSM4(bh[1], bhB + (uint32_t)(16 * STRB) + ko);
            LDSM4(bl[0], bhB + (uint32_t)TILE_B + ko);
            LDSM4(bl[1], bhB + (uint32_t)(TILE_B + 16 * STRB) + ko);
            // hh phase: 8 independent accumulators
            MMA_F16(acc[0][0], ah[0], bh[0][0], bh[0][2]);
            MMA_F16(acc[1][0], ah[1], bh[0][0], bh[0][2]);
            MMA_F16(acc[0][1], ah[0], bh[0][1], bh[0][3]);
            MMA_F16(acc[1][1], ah[1], bh[0][1], bh[0][3]);
            MMA_F16(acc[0][2], ah[0], bh[1][0], bh[1][2]);
            MMA_F16(acc[1][2], ah[1], bh[1][0], bh[1][2]);
            MMA_F16(acc[0][3], ah[0], bh[1][1], bh[1][3]);
            MMA_F16(acc[1][3], ah[1], bh[1][1], bh[1][3]);
            // hl phase
            MMA_F16(acc[0][0], ah[0], bl[0][0], bl[0][2]);
            MMA_F16(acc[1][0], ah[1], bl[0][0], bl[0][2]);
            MMA_F16(acc[0][1], ah[0], bl[0][1], bl[0][3]);
            MMA_F16(acc[1][1], ah[1], bl[0][1], bl[0][3]);
            MMA_F16(acc[0][2], ah[0], bl[1][0], bl[1][2]);
            MMA_F16(acc[1][2], ah[1], bl[1][0], bl[1][2]);
            MMA_F16(acc[0][3], ah[0], bl[1][1], bl[1][3]);
            MMA_F16(acc[1][3], ah[1], bl[1][1], bl[1][3]);
        }
    }
}

// Fragment->(row,col) 2-MMA core: row = mw*32 + mt*16 + (lane>>2) + 8*h ;
// col = nwq*32 + nt*8 + (lane&3)*2 + {0,1}.

// ---------------- 0) converts -------------------------------------------------
__device__ __forceinline__ void split_store(float x, __half* hi,
                                            __half* lo, size_t i)
{
    __half h = __float2half_rn(x);
    hi[i] = h;
    lo[i] = __float2half_rn(x - __half2float(h));
}

__global__ void convert_x_kernel(const float* __restrict__ src) {
    const int i4 = blockIdx.x * 256 + threadIdx.x;
    const size_t i = (size_t)i4 * 4;
    if (i + 3 < (size_t)BS_ * D_) {
        float4 v = *(const float4*)(src + i);
        __half h0 = __float2half_rn(v.x), h1 = __float2half_rn(v.y);
        __half h2 = __float2half_rn(v.z), h3 = __float2half_rn(v.w);
        __half2 hp0 = __halves2half2(h0, h1), hp1 = __halves2half2(h2, h3);
        __half2 lp0 = __halves2half2(__float2half_rn(v.x - __half2float(h0)),
                                     __float2half_rn(v.y - __half2float(h1)));
        __half2 lp1 = __halves2half2(__float2half_rn(v.z - __half2float(h2)),
                                     __float2half_rn(v.w - __half2float(h3)));
        *(__half2*)(g_Xhi + i)     = hp0;
        *(__half2*)(g_Xhi + i + 2) = hp1;
        *(__half2*)(g_Xlo + i)     = lp0;
        *(__half2*)(g_Xlo + i + 2) = lp1;
    }
}

__global__ void convert_small_kernel(
    const float* __restrict__ w0, const float* __restrict__ w1,
    const float* __restrict__ w2, const float* __restrict__ w3,
    const float* __restrict__ r0, const float* __restrict__ r1)
{
    const int z = blockIdx.y;
    const float* src;
    __half *hi, *lo;
    int n;
    if (z < 4) {
        src = (z == 0) ? w0 : (z == 1) ? w1 : (z == 2) ? w2 : w3;
        hi = g_Whi[z]; lo = g_Wlo[z]; n = D_ * D_;
    } else {
        src = (z == 4) ? r0 : r1;
        hi = g_Rhi[z - 4]; lo = g_Rlo[z - 4]; n = NREL * D_;
    }
    int i = blockIdx.x * 256 + threadIdx.x;
    if (i < n) split_store(src[i], hi, lo, i);
}

// ---------------- 1) projections (full 3-MMA precision) ----------------------
__global__ void __launch_bounds__(256, 2)
proj_kernel(const float* __restrict__ bq1, const float* __restrict__ bk1,
            const float* __restrict__ bq2, const float* __restrict__ bk2)
{
    const int z = blockIdx.z;
    const float* bias = (z == 0) ? bq1 : (z == 1) ? bk1 : (z == 2) ? bq2 : bk2;
    const float scale = (z == 0 || z == 2) ? 0.0625f : 1.0f;

    const int mBase = blockIdx.y * 128;
    const int nBase = blockIdx.x * 128;

    float acc[2][8][4];
    gemm_mma3(g_Xhi, g_Xlo, g_Whi[z], g_Wlo[z], mBase, nBase, acc);

    const int lane = threadIdx.x & 31, wid = threadIdx.x >> 5;
    const int mw = wid >> 1, nw = wid & 1;

#pragma unroll
    for (int mt = 0; mt < 2; mt++) {
#pragma unroll
        for (int h = 0; h < 2; h++) {
            const int m = mBase + mw * 32 + mt * 16 + (lane >> 2) + 8 * h;
            __half* dhi = g_Phi[z] + (size_t)m * D_;
            __half* dlo = g_Plo[z] + (size_t)m * D_;
#pragma unroll
            for (int nt = 0; nt < 8; nt++) {
                const int col = nBase + nw * 64 + nt * 8 + (lane & 3) * 2;
                float y0 = (acc[mt][nt][h * 2 + 0] + bias[col + 0]) * scale;
                float y1 = (acc[mt][nt][h * 2 + 1] + bias[col + 1]) * scale;
                __half h0 = __float2half_rn(y0);
                __half h1 = __float2half_rn(y1);
                __half2 hp = __halves2half2(h0, h1);
                __half2 lp = __halves2half2(
                    __float2half_rn(y0 - __half2float(h0)),
                    __float2half_rn(y1 - __half2float(h1)));
                *(__half2*)(dhi + col) = hp;
                *(__half2*)(dlo + col) = lp;
            }
        }
    }
}

// ---------------- 2) q_rel: cols 0..127 via GEMM (2-MMA, 512 thr) ------------
__global__ void __launch_bounds__(512, 2)
qr_kernel()
{
    const int head  = blockIdx.z;
    const int mBase = blockIdx.y * 128;

    float acc[2][4][4];
    gemm_mma2(g_Phi[head * 2], g_Rhi[head], g_Rlo[head], mBase, 0, 128, acc);

    const int lane = threadIdx.x & 31, wid = threadIdx.x >> 5;
    const int mw = wid >> 2, nwq = wid & 3;

#pragma unroll
    for (int mt = 0; mt < 2; mt++) {
#pragma unroll
        for (int h = 0; h < 2; h++) {
            const int m = mBase + mw * 32 + mt * 16 + (lane >> 2) + 8 * h;
            float* dst = g_QR[head] + (size_t)m * QRS;
#pragma unroll
            for (int nt = 0; nt < 4; nt++) {
                const int col = nwq * 32 + nt * 8 + (lane & 3) * 2;
                *(float2*)(dst + col) =
                    make_float2(acc[mt][nt][h * 2 + 0], acc[mt][nt][h * 2 + 1]);
            }
        }
    }
}

// ---------------- 2b) q_rel column 128 (rel position +64) via GEMV -----------
__global__ void __launch_bounds__(256)
qr_col_kernel()
{
    const int gw   = blockIdx.x * 8 + (threadIdx.x >> 5);  // 0..2047
    const int lane = threadIdx.x & 31;
    const int head = gw >> 10;
    const int row0 = (gw & 1023) * 16;

    float rf[8];
    {
        const __half* rh = g_Rhi[head] + (size_t)128 * D_ + lane * 8;
        const __half* rl = g_Rlo[head] + (size_t)128 * D_ + lane * 8;
        uint4 vh = *(const uint4*)rh;
        uint4 vl = *(const uint4*)rl;
        const __half* ph = (const __half*)&vh;
        const __half* pl = (const __half*)&vl;
#pragma unroll
        for (int j = 0; j < 8; j++)
            rf[j] = __half2float(ph[j]) + __half2float(pl[j]);
    }

    const __half* Qhi = g_Phi[head * 2];
    const __half* Qlo = g_Plo[head * 2];

    for (int r = 0; r < 16; r++) {
        const int row = row0 + r;
        uint4 vh = *(const uint4*)(Qhi + (size_t)row * D_ + lane * 8);
        uint4 vl = *(const uint4*)(Qlo + (size_t)row * D_ + lane * 8);
        const __half* ph = (const __half*)&vh;
        const __half* pl = (const __half*)&vl;
        float s = 0.f;
#pragma unroll
        for (int j = 0; j < 8; j++)
            s += (__half2float(ph[j]) + __half2float(pl[j])) * rf[j];
#pragma unroll
        for (int o = 16; o > 0; o >>= 1)
            s += __shfl_xor_sync(0xFFFFFFFF, s, o);
        if (lane == 0) g_QR[head][(size_t)row * QRS + 128] = s;
    }
}

// ---------------- 3) scores (2-MMA, 512 thr) ---------------------------------
__global__ void __launch_bounds__(512, 2)
scores_kernel(const int* __restrict__ mask, float* __restrict__ out)
{
    const int z    = blockIdx.z;
    const int head = z >> 3;
    const int b    = z & 7;
    const int qBase = blockIdx.y * 128;
    const int kBase = blockIdx.x * 128;

    const size_t po = (size_t)b * S_ * D_;
    float acc[2][4][4];
    gemm_mma2(g_Phi[head * 2 + 0] + po,
              g_Phi[head * 2 + 1] + po, g_Plo[head * 2 + 1] + po,
              qBase, kBase, 1 << 30, acc);

    const int lane = threadIdx.x & 31, wid = threadIdx.x >> 5;
    const int mw = wid >> 2, nwq = wid & 3;
    const int* mrow = mask + b * S_;

#pragma unroll
    for (int mt = 0; mt < 2; mt++) {
#pragma unroll
        for (int h = 0; h < 2; h++) {
            const int qg = qBase + mw * 32 + mt * 16 + (lane >> 2) + 8 * h;
            const int mq = mrow[qg];
            const float* qr = g_QR[head] + ((size_t)b * S_ + qg) * QRS;
            float* orow = out + (((size_t)head * B_ + b) * S_ + qg) * S_;
#pragma unroll
            for (int nt = 0; nt < 4; nt++) {
                const int kg = kBase + nwq * 32 + nt * 8 + (lane & 3) * 2;
                int d0 = kg - qg;
                int d1 = d0 + 1;
                d0 = (d0 < -64) ? -64 : ((d0 > 64) ? 64 : d0);
                d1 = (d1 < -64) ? -64 : ((d1 > 64) ? 64 : d1);
                float v0 = acc[mt][nt][h * 2 + 0] + qr[d0 + 64];
                float v1 = acc[mt][nt][h * 2 + 1] + qr[d1 + 64];
                if (mq == 0 || mrow[kg + 0] == 0) v0 = -1e18f;
                if (mq == 0 || mrow[kg + 1] == 0) v1 = -1e18f;
                float2 v = make_float2(v0, v1);
                *(float2*)(orow + kg) = v;
            }
        }
    }
}

// ---------------- launch --------------------------------------------------------
extern "C" void kernel_launch(void* const* d_in, const int* in_sizes, int n_in,
                              void* d_out, int out_size)
{
    const float* repre = (const float*)d_in[0];
    const int*   mask  = (const int*)d_in[1];
    const float* wq1 = (const float*)d_in[2];
    const float* bq1 = (const float*)d_in[3];
    const float* wk1 = (const float*)d_in[4];
    const float* bk1 = (const float*)d_in[5];
    const float* rel1 = (const float*)d_in[6];
    const float* wq2 = (const float*)d_in[7];
    const float* bq2 = (const float*)d_in[8];
    const float* wk2 = (const float*)d_in[9];
    const float* bk2 = (const float*)d_in[10];
    const float* rel2 = (const float*)d_in[11];
    float* out = (float*)d_out;
    (void)in_sizes; (void)n_in; (void)out_size;

    cudaFuncSetAttribute(proj_kernel,
                         cudaFuncAttributeMaxDynamicSharedMemorySize, SMEM4);
    cudaFuncSetAttribute(qr_kernel,
                         cudaFuncAttributeMaxDynamicSharedMemorySize, SMEM3);
    cudaFuncSetAttribute(scores_kernel,
                         cudaFuncAttributeMaxDynamicSharedMemorySize, SMEM3);

    const int NX4 = BS_ * D_ / 4;
    const int NW = D_ * D_;

    convert_x_kernel<<<(NX4 + 255) / 256, 256>>>(repre);
    convert_small_kernel<<<dim3((NW + 255) / 256, 6), 256>>>(
        wq1, wk1, wq2, wk2, rel1, rel2);

    proj_kernel<<<dim3(2, 128, 4), 256, SMEM4>>>(bq1, bk1, bq2, bk2);
    qr_kernel<<<dim3(1, 128, 2), 512, SMEM3>>>();
    qr_col_kernel<<<256, 256>>>();
    scores_kernel<<<dim3(16, 16, 16), 512, SMEM3>>>(mask, out);
}

// round 12
// speedup vs baseline: 1.0930x; 1.0247x over previous
#include <cuda_runtime.h>
#include <cuda_fp16.h>
#include <cstdint>

// ---------------------------------------------------------------------------
// SpanClassifier via portable mma.sync fp16-split GEMMs.
//   B=8, S=2048, D=256, NREL=129
// Round 12: 3-stage cp.async pipeline for the 2-MMA (scores/qr) core --
// loads get two compute periods of cover (wait_group 1), removing the
// per-chunk load stall of the 2-stage loop. 512-thr CTAs, 4x4 warp grid,
// 32x32 warp tiles (R11). Proj keeps 2-stage 3-MMA core; skips Q-lo store.
//   proj:       3 MMAs -> error ~2^-22
//   qr/scores:  2 MMAs (hi*hi + hi_A*lo_B) -> error ~2^-11
// ---------------------------------------------------------------------------

namespace {
constexpr int B_   = 8;
constexpr int S_   = 2048;
constexpr int D_   = 256;
constexpr int NREL = 129;
constexpr int QRS  = 132;
constexpr int BS_  = B_ * S_;   // 16384

constexpr int KC    = 32;                 // k-chunk (fp16 elems)
constexpr int NCH   = D_ / KC;            // 8
constexpr int STRB  = 80;                 // smem row stride bytes (64 data + 16 pad)
constexpr int TILE_B = 128 * STRB;        // 10240 bytes

// proj (3-MMA) staging: 4 tiles, 2 stages
constexpr int T_AHI = 0;
constexpr int T_ALO = TILE_B;
constexpr int T_BHI = 2 * TILE_B;
constexpr int T_BLO = 3 * TILE_B;
constexpr int STAGE4_B = 4 * TILE_B;      // 40960
constexpr int SMEM4 = 2 * STAGE4_B;       // 81920

// scores/qr (2-MMA) staging: 3 tiles, 3 stages
constexpr int T2_A  = 0;
constexpr int T2_BH = TILE_B;
constexpr int T2_BL = 2 * TILE_B;
constexpr int STAGE3_B = 3 * TILE_B;      // 30720
constexpr int SMEM3 = 3 * STAGE3_B;       // 92160
}

// ---------------- scratch (device globals; no runtime allocation) ----------
__device__ __half g_Xhi[BS_ * D_];
__device__ __half g_Xlo[BS_ * D_];
__device__ __half g_Phi[4][BS_ * D_];
__device__ __half g_Plo[4][BS_ * D_];
__device__ __half g_Whi[4][D_ * D_];
__device__ __half g_Wlo[4][D_ * D_];
__device__ __half g_Rhi[2][NREL * D_];
__device__ __half g_Rlo[2][NREL * D_];
__device__ float g_QR[2][BS_ * QRS];

// ---------------- PTX helpers ----------------------------------------------
__device__ __forceinline__ uint32_t smem_u32(const void* p) {
    uint32_t a;
    asm("{ .reg .u64 t; cvta.to.shared.u64 t, %1; cvt.u32.u64 %0, t; }"
        : "=r"(a) : "l"(p));
    return a;
}

#define LDSM4(R, addr)                                                        \
    asm volatile("ldmatrix.sync.aligned.m8n8.x4.shared.b16 {%0,%1,%2,%3}, [%4];" \
                 : "=r"((R)[0]), "=r"((R)[1]), "=r"((R)[2]), "=r"((R)[3])     \
                 : "r"(addr))

#define MMA_F16(C, A, B0, B1)                                                 \
    asm volatile("mma.sync.aligned.m16n8k16.row.col.f32.f16.f16.f32 "         \
                 "{%0,%1,%2,%3},{%4,%5,%6,%7},{%8,%9},{%0,%1,%2,%3};"         \
                 : "+f"((C)[0]), "+f"((C)[1]), "+f"((C)[2]), "+f"((C)[3])     \
                 : "r"((A)[0]), "r"((A)[1]), "r"((A)[2]), "r"((A)[3]),        \
                   "r"(B0), "r"(B1))

__device__ __forceinline__ void cp16(uint32_t dst, const void* src, bool valid) {
    uint32_t n = valid ? 16u : 0u;
    asm volatile("cp.async.cg.shared.global [%0], [%1], 16, %2;"
                 :: "r"(dst), "l"(src), "r"(n));
}
#define CP_COMMIT() asm volatile("cp.async.commit_group;" ::: "memory")
#define CP_WAIT0()  asm volatile("cp.async.wait_group 0;" ::: "memory")
#define CP_WAIT1()  asm volatile("cp.async.wait_group 1;" ::: "memory")

extern __shared__ char dynsm[];

// ============================================================================
//  (A) 3-MMA core for proj: 256 threads, 4x2 warp grid, 32x64 warp tiles
// ============================================================================
__device__ __forceinline__ void prefetch4(
    uint32_t smstage,
    const __half* __restrict__ Ahi, const __half* __restrict__ Alo,
    const __half* __restrict__ Bhi, const __half* __restrict__ Blo,
    int rowA0, int rowB0, int col0, int tid)
{
#pragma unroll
    for (int t = 0; t < 2; t++) {
        const int idx = t * 256 + tid;     // 0..511
        const int r   = idx >> 2;
        const int c4  = idx & 3;
        const uint32_t so = (uint32_t)(r * STRB + c4 * 16);
        const size_t gao = (size_t)(rowA0 + r) * D_ + col0 + c4 * 8;
        cp16(smstage + T_AHI + so, Ahi + gao, true);
        cp16(smstage + T_ALO + so, Alo + gao, true);
        const size_t gbo = (size_t)(rowB0 + r) * D_ + col0 + c4 * 8;
        cp16(smstage + T_BHI + so, Bhi + gbo, true);
        cp16(smstage + T_BLO + so, Blo + gbo, true);
    }
}

__device__ __forceinline__ void gemm_mma3(
    const __half* __restrict__ Ahi, const __half* __restrict__ Alo,
    const __half* __restrict__ Bhi, const __half* __restrict__ Blo,
    int rowA0, int rowB0, float acc[2][8][4])
{
    const int tid  = threadIdx.x;
    const int lane = tid & 31;
    const int wid  = tid >> 5;
    const int mw   = wid >> 1;   // 0..3
    const int nw   = wid & 1;    // 0..1

    const uint32_t smb = smem_u32(dynsm);
    const int lrow       = lane & 15;
    const uint32_t khalf = (uint32_t)((lane >> 4) * 16);
    const uint32_t aOff = (uint32_t)((mw * 32 + lrow) * STRB) + khalf;
    const uint32_t bOff = (uint32_t)((nw * 64 + lrow) * STRB) + khalf;

#pragma unroll
    for (int mt = 0; mt < 2; mt++)
#pragma unroll
        for (int nt = 0; nt < 8; nt++)
#pragma unroll
            for (int e = 0; e < 4; e++) acc[mt][nt][e] = 0.f;

    prefetch4(smb, Ahi, Alo, Bhi, Blo, rowA0, rowB0, 0, tid);
    CP_COMMIT();

    for (int c = 0; c < NCH; c++) {
        CP_WAIT0();
        __syncthreads();
        if (c + 1 < NCH) {
            prefetch4(smb + ((c + 1) & 1) * STAGE4_B, Ahi, Alo, Bhi, Blo,
                      rowA0, rowB0, (c + 1) * KC, tid);
            CP_COMMIT();
        }
        const uint32_t st = smb + (c & 1) * STAGE4_B;
        const uint32_t aHi = st + T_AHI + aOff;
        const uint32_t bHi = st + T_BHI + bOff;

#pragma unroll
        for (int ks = 0; ks < 2; ks++) {
            const uint32_t ko = (uint32_t)(ks * 32);
            uint32_t ah[2][4], al[2][4];
#pragma unroll
            for (int mt = 0; mt < 2; mt++) {
                LDSM4(ah[mt], aHi + (uint32_t)(mt * 16 * STRB) + ko);
                LDSM4(al[mt], aHi + (uint32_t)(TILE_B + mt * 16 * STRB) + ko);
            }
#pragma unroll
            for (int p = 0; p < 2; p++) {
                uint32_t bh[2][4], bl[2][4];
#pragma unroll
                for (int u = 0; u < 2; u++) {
                    const uint32_t nb = (uint32_t)((2 * p + u) * 16 * STRB) + ko;
                    LDSM4(bh[u], bHi + nb);
                    LDSM4(bl[u], bHi + (uint32_t)TILE_B + nb);
                }
                const int n0 = 4 * p;
                MMA_F16(acc[0][n0 + 0], ah[0], bh[0][0], bh[0][2]);
                MMA_F16(acc[1][n0 + 0], ah[1], bh[0][0], bh[0][2]);
                MMA_F16(acc[0][n0 + 1], ah[0], bh[0][1], bh[0][3]);
                MMA_F16(acc[1][n0 + 1], ah[1], bh[0][1], bh[0][3]);
                MMA_F16(acc[0][n0 + 2], ah[0], bh[1][0], bh[1][2]);
                MMA_F16(acc[1][n0 + 2], ah[1], bh[1][0], bh[1][2]);
                MMA_F16(acc[0][n0 + 3], ah[0], bh[1][1], bh[1][3]);
                MMA_F16(acc[1][n0 + 3], ah[1], bh[1][1], bh[1][3]);
                MMA_F16(acc[0][n0 + 0], ah[0], bl[0][0], bl[0][2]);
                MMA_F16(acc[1][n0 + 0], ah[1], bl[0][0], bl[0][2]);
                MMA_F16(acc[0][n0 + 1], ah[0], bl[0][1], bl[0][3]);
                MMA_F16(acc[1][n0 + 1], ah[1], bl[0][1], bl[0][3]);
                MMA_F16(acc[0][n0 + 2], ah[0], bl[1][0], bl[1][2]);
                MMA_F16(acc[1][n0 + 2], ah[1], bl[1][0], bl[1][2]);
                MMA_F16(acc[0][n0 + 3], ah[0], bl[1][1], bl[1][3]);
                MMA_F16(acc[1][n0 + 3], ah[1], bl[1][1], bl[1][3]);
                MMA_F16(acc[0][n0 + 0], al[0], bh[0][0], bh[0][2]);
                MMA_F16(acc[1][n0 + 0], al[1], bh[0][0], bh[0][2]);
                MMA_F16(acc[0][n0 + 1], al[0], bh[0][1], bh[0][3]);
                MMA_F16(acc[1][n0 + 1], al[1], bh[0][1], bh[0][3]);
                MMA_F16(acc[0][n0 + 2], al[0], bh[1][0], bh[1][2]);
                MMA_F16(acc[1][n0 + 2], al[1], bh[1][0], bh[1][2]);
                MMA_F16(acc[0][n0 + 3], al[0], bh[1][1], bh[1][3]);
                MMA_F16(acc[1][n0 + 3], al[1], bh[1][1], bh[1][3]);
            }
        }
    }
}

// ============================================================================
//  (B) 2-MMA core: 512 threads, 4x4 warp grid, 32x32 warp tiles, 3 stages
// ============================================================================
__device__ __forceinline__ void prefetch3(
    uint32_t smstage,
    const __half* __restrict__ Ahi,
    const __half* __restrict__ Bhi, const __half* __restrict__ Blo,
    int rowA0, int rowB0, int bLim, int col0, int tid)
{
    const int r  = tid >> 2;          // 0..127
    const int c4 = tid & 3;
    const uint32_t so = (uint32_t)(r * STRB + c4 * 16);
    const size_t gao = (size_t)(rowA0 + r) * D_ + col0 + c4 * 8;
    cp16(smstage + T2_A + so, Ahi + gao, true);
    const bool bv = (rowB0 + r) < bLim;
    const int gbr = bv ? (rowB0 + r) : 0;
    const size_t gbo = (size_t)gbr * D_ + col0 + c4 * 8;
    cp16(smstage + T2_BH + so, Bhi + gbo, bv);
    cp16(smstage + T2_BL + so, Blo + gbo, bv);
}

__device__ __forceinline__ void gemm_mma2(
    const __half* __restrict__ Ahi,
    const __half* __restrict__ Bhi, const __half* __restrict__ Blo,
    int rowA0, int rowB0, int bLim, float acc[2][4][4])
{
    const int tid  = threadIdx.x;
    const int lane = tid & 31;
    const int wid  = tid >> 5;       // 0..15
    const int mw   = wid >> 2;       // 0..3
    const int nwq  = wid & 3;        // 0..3

    const uint32_t smb = smem_u32(dynsm);
    const int lrow       = lane & 15;
    const uint32_t khalf = (uint32_t)((lane >> 4) * 16);
    const uint32_t aOff = (uint32_t)((mw * 32 + lrow) * STRB) + khalf;
    const uint32_t bOff = (uint32_t)((nwq * 32 + lrow) * STRB) + khalf;

#pragma unroll
    for (int mt = 0; mt < 2; mt++)
#pragma unroll
        for (int nt = 0; nt < 4; nt++)
#pragma unroll
            for (int e = 0; e < 4; e++) acc[mt][nt][e] = 0.f;

    // 3-stage prologue: chunks 0 and 1 in flight
    prefetch3(smb, Ahi, Bhi, Blo, rowA0, rowB0, bLim, 0, tid);
    CP_COMMIT();
    prefetch3(smb + STAGE3_B, Ahi, Bhi, Blo, rowA0, rowB0, bLim, KC, tid);
    CP_COMMIT();

    int stage_c = 0;   // stage holding chunk c
    for (int c = 0; c < NCH; c++) {
        if (c + 1 < NCH) { CP_WAIT1(); } else { CP_WAIT0(); }
        __syncthreads();   // chunk c visible to all; all warps done with c-1

        if (c + 2 < NCH) {
            int stage_n = stage_c + 2;
            if (stage_n >= 3) stage_n -= 3;
            prefetch3(smb + stage_n * STAGE3_B, Ahi, Bhi, Blo,
                      rowA0, rowB0, bLim, (c + 2) * KC, tid);
            CP_COMMIT();
        }

        const uint32_t st = smb + stage_c * STAGE3_B;
        if (++stage_c == 3) stage_c = 0;
        const uint32_t aB  = st + T2_A + aOff;
        const uint32_t bhB = st + T2_BH + bOff;

#pragma unroll
        for (int ks = 0; ks < 2; ks++) {
            const uint32_t ko = (uint32_t)(ks * 32);
            uint32_t ah[2][4], bh[2][4], bl[2][4];
            LDSM4(ah[0], aB + ko);
            LDSM4(ah[1], aB + (uint32_t)(16 * STRB) + ko);
            LDSM4(bh[0], bhB + ko);
            LDSM4(bh[1], bhB + (uint32_t)(16 * STRB) + ko);
            LDSM4(bl[0], bhB + (uint32_t)TILE_B + ko);
            LDSM4(bl[1], bhB + (uint32_t)(TILE_B + 16 * STRB) + ko);
            // hh phase: 8 independent accumulators
            MMA_F16(acc[0][0], ah[0], bh[0][0], bh[0][2]);
            MMA_F16(acc[1][0], ah[1], bh[0][0], bh[0][2]);
            MMA_F16(acc[0][1], ah[0], bh[0][1], bh[0][3]);
            MMA_F16(acc[1][1], ah[1], bh[0][1], bh[0][3]);
            MMA_F16(acc[0][2], ah[0], bh[1][0], bh[1][2]);
            MMA_F16(acc[1][2], ah[1], bh[1][0], bh[1][2]);
            MMA_F16(acc[0][3], ah[0], bh[1][1], bh[1][3]);
            MMA_F16(acc[1][3], ah[1], bh[1][1], bh[1][3]);
            // hl phase
            MMA_F16(acc[0][0], ah[0], bl[0][0], bl[0][2]);
            MMA_F16(acc[1][0], ah[1], bl[0][0], bl[0][2]);
            MMA_F16(acc[0][1], ah[0], bl[0][1], bl[0][3]);
            MMA_F16(acc[1][1], ah[1], bl[0][1], bl[0][3]);
            MMA_F16(acc[0][2], ah[0], bl[1][0], bl[1][2]);
            MMA_F16(acc[1][2], ah[1], bl[1][0], bl[1][2]);
            MMA_F16(acc[0][3], ah[0], bl[1][1], bl[1][3]);
            MMA_F16(acc[1][3], ah[1], bl[1][1], bl[1][3]);
        }
    }
}

// Fragment->(row,col) 2-MMA core: row = mw*32 + mt*16 + (lane>>2) + 8*h ;
// col = nwq*32 + nt*8 + (lane&3)*2 + {0,1}.

// ---------------- 0) converts -------------------------------------------------
__device__ __forceinline__ void split_store(float x, __half* hi,
                                            __half* lo, size_t i)
{
    __half h = __float2half_rn(x);
    hi[i] = h;
    lo[i] = __float2half_rn(x - __half2float(h));
}

__global__ void convert_x_kernel(const float* __restrict__ src) {
    const int i4 = blockIdx.x * 256 + threadIdx.x;
    const size_t i = (size_t)i4 * 4;
    if (i + 3 < (size_t)BS_ * D_) {
        float4 v = *(const float4*)(src + i);
        __half h0 = __float2half_rn(v.x), h1 = __float2half_rn(v.y);
        __half h2 = __float2half_rn(v.z), h3 = __float2half_rn(v.w);
        __half2 hp0 = __halves2half2(h0, h1), hp1 = __halves2half2(h2, h3);
        __half2 lp0 = __halves2half2(__float2half_rn(v.x - __half2float(h0)),
                                     __float2half_rn(v.y - __half2float(h1)));
        __half2 lp1 = __halves2half2(__float2half_rn(v.z - __half2float(h2)),
                                     __float2half_rn(v.w - __half2float(h3)));
        *(__half2*)(g_Xhi + i)     = hp0;
        *(__half2*)(g_Xhi + i + 2) = hp1;
        *(__half2*)(g_Xlo + i)     = lp0;
        *(__half2*)(g_Xlo + i + 2) = lp1;
    }
}

__global__ void convert_small_kernel(
    const float* __restrict__ w0, const float* __restrict__ w1,
    const float* __restrict__ w2, const float* __restrict__ w3,
    const float* __restrict__ r0, const float* __restrict__ r1)
{
    const int z = blockIdx.y;
    const float* src;
    __half *hi, *lo;
    int n;
    if (z < 4) {
        src = (z == 0) ? w0 : (z == 1) ? w1 : (z == 2) ? w2 : w3;
        hi = g_Whi[z]; lo = g_Wlo[z]; n = D_ * D_;
    } else {
        src = (z == 4) ? r0 : r1;
        hi = g_Rhi[z - 4]; lo = g_Rlo[z - 4]; n = NREL * D_;
    }
    int i = blockIdx.x * 256 + threadIdx.x;
    if (i < n) split_store(src[i], hi, lo, i);
}

// ---------------- 1) projections (full 3-MMA precision) ----------------------
// Q-lo (z=0,2) is never consumed downstream -> skip that store.
__global__ void __launch_bounds__(256, 2)
proj_kernel(const float* __restrict__ bq1, const float* __restrict__ bk1,
            const float* __restrict__ bq2, const float* __restrict__ bk2)
{
    const int z = blockIdx.z;
    const float* bias = (z == 0) ? bq1 : (z == 1) ? bk1 : (z == 2) ? bq2 : bk2;
    const float scale = (z == 0 || z == 2) ? 0.0625f : 1.0f;
    const bool storeLo = (z == 1 || z == 3);

    const int mBase = blockIdx.y * 128;
    const int nBase = blockIdx.x * 128;

    float acc[2][8][4];
    gemm_mma3(g_Xhi, g_Xlo, g_Whi[z], g_Wlo[z], mBase, nBase, acc);

    const int lane = threadIdx.x & 31, wid = threadIdx.x >> 5;
    const int mw = wid >> 1, nw = wid & 1;

#pragma unroll
    for (int mt = 0; mt < 2; mt++) {
#pragma unroll
        for (int h = 0; h < 2; h++) {
            const int m = mBase + mw * 32 + mt * 16 + (lane >> 2) + 8 * h;
            __half* dhi = g_Phi[z] + (size_t)m * D_;
            __half* dlo = g_Plo[z] + (size_t)m * D_;
#pragma unroll
            for (int nt = 0; nt < 8; nt++) {
                const int col = nBase + nw * 64 + nt * 8 + (lane & 3) * 2;
                float y0 = (acc[mt][nt][h * 2 + 0] + bias[col + 0]) * scale;
                float y1 = (acc[mt][nt][h * 2 + 1] + bias[col + 1]) * scale;
                __half h0 = __float2half_rn(y0);
                __half h1 = __float2half_rn(y1);
                *(__half2*)(dhi + col) = __halves2half2(h0, h1);
                if (storeLo) {
                    __half2 lp = __halves2half2(
                        __float2half_rn(y0 - __half2float(h0)),
                        __float2half_rn(y1 - __half2float(h1)));
                    *(__half2*)(dlo + col) = lp;
                }
            }
        }
    }
}

// ---------------- 2) q_rel: cols 0..127 via GEMM (2-MMA, 512 thr) ------------
__global__ void __launch_bounds__(512, 2)
qr_kernel()
{
    const int head  = blockIdx.z;
    const int mBase = blockIdx.y * 128;

    float acc[2][4][4];
    gemm_mma2(g_Phi[head * 2], g_Rhi[head], g_Rlo[head], mBase, 0, 128, acc);

    const int lane = threadIdx.x & 31, wid = threadIdx.x >> 5;
    const int mw = wid >> 2, nwq = wid & 3;

#pragma unroll
    for (int mt = 0; mt < 2; mt++) {
#pragma unroll
        for (int h = 0; h < 2; h++) {
            const int m = mBase + mw * 32 + mt * 16 + (lane >> 2) + 8 * h;
            float* dst = g_QR[head] + (size_t)m * QRS;
#pragma unroll
            for (int nt = 0; nt < 4; nt++) {
                const int col = nwq * 32 + nt * 8 + (lane & 3) * 2;
                *(float2*)(dst + col) =
                    make_float2(acc[mt][nt][h * 2 + 0], acc[mt][nt][h * 2 + 1]);
            }
        }
    }
}

// ---------------- 2b) q_rel column 128 (rel position +64) via GEMV -----------
__global__ void __launch_bounds__(256)
qr_col_kernel()
{
    const int gw   = blockIdx.x * 8 + (threadIdx.x >> 5);  // 0..2047
    const int lane = threadIdx.x & 31;
    const int head = gw >> 10;
    const int row0 = (gw & 1023) * 16;

    float rf[8];
    {
        const __half* rh = g_Rhi[head] + (size_t)128 * D_ + lane * 8;
        const __half* rl = g_Rlo[head] + (size_t)128 * D_ + lane * 8;
        uint4 vh = *(const uint4*)rh;
        uint4 vl = *(const uint4*)rl;
        const __half* ph = (const __half*)&vh;
        const __half* pl = (const __half*)&vl;
#pragma unroll
        for (int j = 0; j < 8; j++)
            rf[j] = __half2float(ph[j]) + __half2float(pl[j]);
    }

    const __half* Qhi = g_Phi[head * 2];

    for (int r = 0; r < 16; r++) {
        const int row = row0 + r;
        uint4 vh = *(const uint4*)(Qhi + (size_t)row * D_ + lane * 8);
        const __half* ph = (const __half*)&vh;
        float s = 0.f;
#pragma unroll
        for (int j = 0; j < 8; j++)
            s += __half2float(ph[j]) * rf[j];
#pragma unroll
        for (int o = 16; o > 0; o >>= 1)
            s += __shfl_xor_sync(0xFFFFFFFF, s, o);
        if (lane == 0) g_QR[head][(size_t)row * QRS + 128] = s;
    }
}

// ---------------- 3) scores (2-MMA, 512 thr) ---------------------------------
__global__ void __launch_bounds__(512, 2)
scores_kernel(const int* __restrict__ mask, float* __restrict__ out)
{
    const int z    = blockIdx.z;
    const int head = z >> 3;
    const int b    = z & 7;
    const int qBase = blockIdx.y * 128;
    const int kBase = blockIdx.x * 128;

    const size_t po = (size_t)b * S_ * D_;
    float acc[2][4][4];
    gemm_mma2(g_Phi[head * 2 + 0] + po,
              g_Phi[head * 2 + 1] + po, g_Plo[head * 2 + 1] + po,
              qBase, kBase, 1 << 30, acc);

    const int lane = threadIdx.x & 31, wid = threadIdx.x >> 5;
    const int mw = wid >> 2, nwq = wid & 3;
    const int* mrow = mask + b * S_;

#pragma unroll
    for (int mt = 0; mt < 2; mt++) {
#pragma unroll
        for (int h = 0; h < 2; h++) {
            const int qg = qBase + mw * 32 + mt * 16 + (lane >> 2) + 8 * h;
            const int mq = mrow[qg];
            const float* qr = g_QR[head] + ((size_t)b * S_ + qg) * QRS;
            float* orow = out + (((size_t)head * B_ + b) * S_ + qg) * S_;
#pragma unroll
            for (int nt = 0; nt < 4; nt++) {
                const int kg = kBase + nwq * 32 + nt * 8 + (lane & 3) * 2;
                int d0 = kg - qg;
                int d1 = d0 + 1;
                d0 = (d0 < -64) ? -64 : ((d0 > 64) ? 64 : d0);
                d1 = (d1 < -64) ? -64 : ((d1 > 64) ? 64 : d1);
                float v0 = acc[mt][nt][h * 2 + 0] + qr[d0 + 64];
                float v1 = acc[mt][nt][h * 2 + 1] + qr[d1 + 64];
                if (mq == 0 || mrow[kg + 0] == 0) v0 = -1e18f;
                if (mq == 0 || mrow[kg + 1] == 0) v1 = -1e18f;
                float2 v = make_float2(v0, v1);
                *(float2*)(orow + kg) = v;
            }
        }
    }
}

// ---------------- launch --------------------------------------------------------
extern "C" void kernel_launch(void* const* d_in, const int* in_sizes, int n_in,
                              void* d_out, int out_size)
{
    const float* repre = (const float*)d_in[0];
    const int*   mask  = (const int*)d_in[1];
    const float* wq1 = (const float*)d_in[2];
    const float* bq1 = (const float*)d_in[3];
    const float* wk1 = (const float*)d_in[4];
    const float* bk1 = (const float*)d_in[5];
    const float* rel1 = (const float*)d_in[6];
    const float* wq2 = (const float*)d_in[7];
    const float* bq2 = (const float*)d_in[8];
    const float* wk2 = (const float*)d_in[9];
    const float* bk2 = (const float*)d_in[10];
    const float* rel2 = (const float*)d_in[11];
    float* out = (float*)d_out;
    (void)in_sizes; (void)n_in; (void)out_size;

    cudaFuncSetAttribute(proj_kernel,
                         cudaFuncAttributeMaxDynamicSharedMemorySize, SMEM4);
    cudaFuncSetAttribute(qr_kernel,
                         cudaFuncAttributeMaxDynamicSharedMemorySize, SMEM3);
    cudaFuncSetAttribute(scores_kernel,
                         cudaFuncAttributeMaxDynamicSharedMemorySize, SMEM3);

    const int NX4 = BS_ * D_ / 4;
    const int NW = D_ * D_;

    convert_x_kernel<<<(NX4 + 255) / 256, 256>>>(repre);
    convert_small_kernel<<<dim3((NW + 255) / 256, 6), 256>>>(
        wq1, wk1, wq2, wk2, rel1, rel2);

    proj_kernel<<<dim3(2, 128, 4), 256, SMEM4>>>(bq1, bk1, bq2, bk2);
    qr_kernel<<<dim3(1, 128, 2), 512, SMEM3>>>();
    qr_col_kernel<<<256, 256>>>();
    scores_kernel<<<dim3(16, 16, 16), 512, SMEM3>>>(mask, out);
}

// round 13
// speedup vs baseline: 1.3629x; 1.2469x over previous
#include <cuda_runtime.h>
#include <cuda_fp16.h>
#include <cstdint>

// ---------------------------------------------------------------------------
// SpanClassifier via portable mma.sync fp16-split GEMMs.
//   B=8, S=2048, D=256, NREL=129
// Round 13: scores drops the K_lo MMA -> single hi*hi MMA (error budget:
// A-side 2^-11 (measured 2.07e-4) + independent B-side 2^-11 => ~3-4e-4,
// still < 1e-3). qr keeps 2 MMAs; proj keeps 3 MMAs.
// scores: 2-tile stages, 4-stage cp.async pipeline; qr: 3-tile, 3-stage.
// 512-thr CTAs, 4x4 warp grid, 32x32 warp tiles for scores/qr.
// ---------------------------------------------------------------------------

namespace {
constexpr int B_   = 8;
constexpr int S_   = 2048;
constexpr int D_   = 256;
constexpr int NREL = 129;
constexpr int QRS  = 132;
constexpr int BS_  = B_ * S_;   // 16384

constexpr int KC    = 32;                 // k-chunk (fp16 elems)
constexpr int NCH   = D_ / KC;            // 8
constexpr int STRB  = 80;                 // smem row stride bytes (64 data + 16 pad)
constexpr int TILE_B = 128 * STRB;        // 10240 bytes

// proj (3-MMA) staging: 4 tiles, 2 stages
constexpr int T_AHI = 0;
constexpr int T_ALO = TILE_B;
constexpr int T_BHI = 2 * TILE_B;
constexpr int T_BLO = 3 * TILE_B;
constexpr int STAGE4_B = 4 * TILE_B;      // 40960
constexpr int SMEM4 = 2 * STAGE4_B;       // 81920

// 2-MMA (qr): 3 tiles x 3 stages = 92160 ; 1-MMA (scores): 2 tiles x 4 = 81920
constexpr int SMEM_QR = 3 * 3 * TILE_B;   // 92160
constexpr int SMEM_SC = 4 * 2 * TILE_B;   // 81920
}

// ---------------- scratch (device globals; no runtime allocation) ----------
__device__ __half g_Xhi[BS_ * D_];
__device__ __half g_Xlo[BS_ * D_];
__device__ __half g_Phi[4][BS_ * D_];
__device__ __half g_Plo[4][BS_ * D_];
__device__ __half g_Whi[4][D_ * D_];
__device__ __half g_Wlo[4][D_ * D_];
__device__ __half g_Rhi[2][NREL * D_];
__device__ __half g_Rlo[2][NREL * D_];
__device__ float g_QR[2][BS_ * QRS];

// ---------------- PTX helpers ----------------------------------------------
__device__ __forceinline__ uint32_t smem_u32(const void* p) {
    uint32_t a;
    asm("{ .reg .u64 t; cvta.to.shared.u64 t, %1; cvt.u32.u64 %0, t; }"
        : "=r"(a) : "l"(p));
    return a;
}

#define LDSM4(R, addr)                                                        \
    asm volatile("ldmatrix.sync.aligned.m8n8.x4.shared.b16 {%0,%1,%2,%3}, [%4];" \
                 : "=r"((R)[0]), "=r"((R)[1]), "=r"((R)[2]), "=r"((R)[3])     \
                 : "r"(addr))

#define MMA_F16(C, A, B0, B1)                                                 \
    asm volatile("mma.sync.aligned.m16n8k16.row.col.f32.f16.f16.f32 "         \
                 "{%0,%1,%2,%3},{%4,%5,%6,%7},{%8,%9},{%0,%1,%2,%3};"         \
                 : "+f"((C)[0]), "+f"((C)[1]), "+f"((C)[2]), "+f"((C)[3])     \
                 : "r"((A)[0]), "r"((A)[1]), "r"((A)[2]), "r"((A)[3]),        \
                   "r"(B0), "r"(B1))

__device__ __forceinline__ void cp16(uint32_t dst, const void* src, bool valid) {
    uint32_t n = valid ? 16u : 0u;
    asm volatile("cp.async.cg.shared.global [%0], [%1], 16, %2;"
                 :: "r"(dst), "l"(src), "r"(n));
}
#define CP_COMMIT() asm volatile("cp.async.commit_group;" ::: "memory")
#define CP_WAIT(n)  asm volatile("cp.async.wait_group %0;" :: "n"(n) : "memory")

extern __shared__ char dynsm[];

// ============================================================================
//  (A) 3-MMA core for proj: 256 threads, 4x2 warp grid, 32x64 warp tiles
// ============================================================================
__device__ __forceinline__ void prefetch4(
    uint32_t smstage,
    const __half* __restrict__ Ahi, const __half* __restrict__ Alo,
    const __half* __restrict__ Bhi, const __half* __restrict__ Blo,
    int rowA0, int rowB0, int col0, int tid)
{
#pragma unroll
    for (int t = 0; t < 2; t++) {
        const int idx = t * 256 + tid;     // 0..511
        const int r   = idx >> 2;
        const int c4  = idx & 3;
        const uint32_t so = (uint32_t)(r * STRB + c4 * 16);
        const size_t gao = (size_t)(rowA0 + r) * D_ + col0 + c4 * 8;
        cp16(smstage + T_AHI + so, Ahi + gao, true);
        cp16(smstage + T_ALO + so, Alo + gao, true);
        const size_t gbo = (size_t)(rowB0 + r) * D_ + col0 + c4 * 8;
        cp16(smstage + T_BHI + so, Bhi + gbo, true);
        cp16(smstage + T_BLO + so, Blo + gbo, true);
    }
}

__device__ __forceinline__ void gemm_mma3(
    const __half* __restrict__ Ahi, const __half* __restrict__ Alo,
    const __half* __restrict__ Bhi, const __half* __restrict__ Blo,
    int rowA0, int rowB0, float acc[2][8][4])
{
    const int tid  = threadIdx.x;
    const int lane = tid & 31;
    const int wid  = tid >> 5;
    const int mw   = wid >> 1;   // 0..3
    const int nw   = wid & 1;    // 0..1

    const uint32_t smb = smem_u32(dynsm);
    const int lrow       = lane & 15;
    const uint32_t khalf = (uint32_t)((lane >> 4) * 16);
    const uint32_t aOff = (uint32_t)((mw * 32 + lrow) * STRB) + khalf;
    const uint32_t bOff = (uint32_t)((nw * 64 + lrow) * STRB) + khalf;

#pragma unroll
    for (int mt = 0; mt < 2; mt++)
#pragma unroll
        for (int nt = 0; nt < 8; nt++)
#pragma unroll
            for (int e = 0; e < 4; e++) acc[mt][nt][e] = 0.f;

    prefetch4(smb, Ahi, Alo, Bhi, Blo, rowA0, rowB0, 0, tid);
    CP_COMMIT();

    for (int c = 0; c < NCH; c++) {
        if (c + 1 < NCH) { CP_WAIT(1); } else { CP_WAIT(0); }
        // NOTE: with 2 stages we must wait for chunk c fully: group for chunk
        // c is the older one; after commit of c+1 there are 2 groups, wait 1
        // leaves newest outstanding -> chunk c resident. For c=NCH-1 wait 0.
        __syncthreads();
        if (c + 1 < NCH) {
            prefetch4(smb + ((c + 1) & 1) * STAGE4_B, Ahi, Alo, Bhi, Blo,
                      rowA0, rowB0, (c + 1) * KC, tid);
            CP_COMMIT();
        }
        const uint32_t st = smb + (c & 1) * STAGE4_B;
        const uint32_t aHi = st + T_AHI + aOff;
        const uint32_t bHi = st + T_BHI + bOff;

#pragma unroll
        for (int ks = 0; ks < 2; ks++) {
            const uint32_t ko = (uint32_t)(ks * 32);
            uint32_t ah[2][4], al[2][4];
#pragma unroll
            for (int mt = 0; mt < 2; mt++) {
                LDSM4(ah[mt], aHi + (uint32_t)(mt * 16 * STRB) + ko);
                LDSM4(al[mt], aHi + (uint32_t)(TILE_B + mt * 16 * STRB) + ko);
            }
#pragma unroll
            for (int p = 0; p < 2; p++) {
                uint32_t bh[2][4], bl[2][4];
#pragma unroll
                for (int u = 0; u < 2; u++) {
                    const uint32_t nb = (uint32_t)((2 * p + u) * 16 * STRB) + ko;
                    LDSM4(bh[u], bHi + nb);
                    LDSM4(bl[u], bHi + (uint32_t)TILE_B + nb);
                }
                const int n0 = 4 * p;
                MMA_F16(acc[0][n0 + 0], ah[0], bh[0][0], bh[0][2]);
                MMA_F16(acc[1][n0 + 0], ah[1], bh[0][0], bh[0][2]);
                MMA_F16(acc[0][n0 + 1], ah[0], bh[0][1], bh[0][3]);
                MMA_F16(acc[1][n0 + 1], ah[1], bh[0][1], bh[0][3]);
                MMA_F16(acc[0][n0 + 2], ah[0], bh[1][0], bh[1][2]);
                MMA_F16(acc[1][n0 + 2], ah[1], bh[1][0], bh[1][2]);
                MMA_F16(acc[0][n0 + 3], ah[0], bh[1][1], bh[1][3]);
                MMA_F16(acc[1][n0 + 3], ah[1], bh[1][1], bh[1][3]);
                MMA_F16(acc[0][n0 + 0], ah[0], bl[0][0], bl[0][2]);
                MMA_F16(acc[1][n0 + 0], ah[1], bl[0][0], bl[0][2]);
                MMA_F16(acc[0][n0 + 1], ah[0], bl[0][1], bl[0][3]);
                MMA_F16(acc[1][n0 + 1], ah[1], bl[0][1], bl[0][3]);
                MMA_F16(acc[0][n0 + 2], ah[0], bl[1][0], bl[1][2]);
                MMA_F16(acc[1][n0 + 2], ah[1], bl[1][0], bl[1][2]);
                MMA_F16(acc[0][n0 + 3], ah[0], bl[1][1], bl[1][3]);
                MMA_F16(acc[1][n0 + 3], ah[1], bl[1][1], bl[1][3]);
                MMA_F16(acc[0][n0 + 0], al[0], bh[0][0], bh[0][2]);
                MMA_F16(acc[1][n0 + 0], al[1], bh[0][0], bh[0][2]);
                MMA_F16(acc[0][n0 + 1], al[0], bh[0][1], bh[0][3]);
                MMA_F16(acc[1][n0 + 1], al[1], bh[0][1], bh[0][3]);
                MMA_F16(acc[0][n0 + 2], al[0], bh[1][0], bh[1][2]);
                MMA_F16(acc[1][n0 + 2], al[1], bh[1][0], bh[1][2]);
                MMA_F16(acc[0][n0 + 3], al[0], bh[1][1], bh[1][3]);
                MMA_F16(acc[1][n0 + 3], al[1], bh[1][1], bh[1][3]);
            }
        }
    }
}

// ============================================================================
//  (B) templated 1/2-MMA core: 512 threads, 4x4 warp grid, 32x32 warp tiles
//  NMMA=2: tiles {A, BH, BL}, NSTAGE=3. NMMA=1: tiles {A, BH}, NSTAGE=4.
// ============================================================================
template <int NMMA, int NSTAGE>
__device__ __forceinline__ void prefetchN(
    uint32_t smstage,
    const __half* __restrict__ Ahi,
    const __half* __restrict__ Bhi, const __half* __restrict__ Blo,
    int rowA0, int rowB0, int bLim, int col0, int tid)
{
    const int r  = tid >> 2;          // 0..127
    const int c4 = tid & 3;
    const uint32_t so = (uint32_t)(r * STRB + c4 * 16);
    const size_t gao = (size_t)(rowA0 + r) * D_ + col0 + c4 * 8;
    cp16(smstage + so, Ahi + gao, true);
    const bool bv = (rowB0 + r) < bLim;
    const int gbr = bv ? (rowB0 + r) : 0;
    const size_t gbo = (size_t)gbr * D_ + col0 + c4 * 8;
    cp16(smstage + (uint32_t)TILE_B + so, Bhi + gbo, bv);
    if (NMMA == 2)
        cp16(smstage + (uint32_t)(2 * TILE_B) + so, Blo + gbo, bv);
}

template <int NMMA, int NSTAGE>
__device__ __forceinline__ void gemm_mmaN(
    const __half* __restrict__ Ahi,
    const __half* __restrict__ Bhi, const __half* __restrict__ Blo,
    int rowA0, int rowB0, int bLim, float acc[2][4][4])
{
    constexpr int STG_B = (1 + NMMA) * TILE_B;

    const int tid  = threadIdx.x;
    const int lane = tid & 31;
    const int wid  = tid >> 5;       // 0..15
    const int mw   = wid >> 2;       // 0..3
    const int nwq  = wid & 3;        // 0..3

    const uint32_t smb = smem_u32(dynsm);
    const int lrow       = lane & 15;
    const uint32_t khalf = (uint32_t)((lane >> 4) * 16);
    const uint32_t aOff = (uint32_t)((mw * 32 + lrow) * STRB) + khalf;
    const uint32_t bOff = (uint32_t)((nwq * 32 + lrow) * STRB) + khalf;

#pragma unroll
    for (int mt = 0; mt < 2; mt++)
#pragma unroll
        for (int nt = 0; nt < 4; nt++)
#pragma unroll
            for (int e = 0; e < 4; e++) acc[mt][nt][e] = 0.f;

    // prologue: NSTAGE-1 chunks in flight
#pragma unroll
    for (int s = 0; s < NSTAGE - 1; s++) {
        prefetchN<NMMA, NSTAGE>(smb + s * STG_B, Ahi, Bhi, Blo,
                                rowA0, rowB0, bLim, s * KC, tid);
        CP_COMMIT();
    }

    int stage_c = 0;   // stage holding chunk c
    for (int c = 0; c < NCH; c++) {
        // leave min(NSTAGE-2, NCH-1-c) groups outstanding
        const int outst = NCH - 1 - c;
        if (NSTAGE == 4) {
            if (outst >= 2)      { CP_WAIT(2); }
            else if (outst == 1) { CP_WAIT(1); }
            else                 { CP_WAIT(0); }
        } else {
            if (outst >= 1)      { CP_WAIT(1); }
            else                 { CP_WAIT(0); }
        }
        __syncthreads();   // chunk c visible to all; all warps done with c-1

        if (c + NSTAGE - 1 < NCH) {
            int stage_n = stage_c + NSTAGE - 1;
            if (stage_n >= NSTAGE) stage_n -= NSTAGE;
            prefetchN<NMMA, NSTAGE>(smb + stage_n * STG_B, Ahi, Bhi, Blo,
                                    rowA0, rowB0, bLim,
                                    (c + NSTAGE - 1) * KC, tid);
            CP_COMMIT();
        }

        const uint32_t st = smb + stage_c * STG_B;
        if (++stage_c == NSTAGE) stage_c = 0;
        const uint32_t aB  = st + aOff;
        const uint32_t bhB = st + (uint32_t)TILE_B + bOff;

#pragma unroll
        for (int ks = 0; ks < 2; ks++) {
            const uint32_t ko = (uint32_t)(ks * 32);
            uint32_t ah[2][4], bh[2][4];
            LDSM4(ah[0], aB + ko);
            LDSM4(ah[1], aB + (uint32_t)(16 * STRB) + ko);
            LDSM4(bh[0], bhB + ko);
            LDSM4(bh[1], bhB + (uint32_t)(16 * STRB) + ko);
            // hh phase: 8 independent accumulators
            MMA_F16(acc[0][0], ah[0], bh[0][0], bh[0][2]);
            MMA_F16(acc[1][0], ah[1], bh[0][0], bh[0][2]);
            MMA_F16(acc[0][1], ah[0], bh[0][1], bh[0][3]);
            MMA_F16(acc[1][1], ah[1], bh[0][1], bh[0][3]);
            MMA_F16(acc[0][2], ah[0], bh[1][0], bh[1][2]);
            MMA_F16(acc[1][2], ah[1], bh[1][0], bh[1][2]);
            MMA_F16(acc[0][3], ah[0], bh[1][1], bh[1][3]);
            MMA_F16(acc[1][3], ah[1], bh[1][1], bh[1][3]);
            if (NMMA == 2) {
                uint32_t bl[2][4];
                LDSM4(bl[0], bhB + (uint32_t)TILE_B + ko);
                LDSM4(bl[1], bhB + (uint32_t)(TILE_B + 16 * STRB) + ko);
                MMA_F16(acc[0][0], ah[0], bl[0][0], bl[0][2]);
                MMA_F16(acc[1][0], ah[1], bl[0][0], bl[0][2]);
                MMA_F16(acc[0][1], ah[0], bl[0][1], bl[0][3]);
                MMA_F16(acc[1][1], ah[1], bl[0][1], bl[0][3]);
                MMA_F16(acc[0][2], ah[0], bl[1][0], bl[1][2]);
                MMA_F16(acc[1][2], ah[1], bl[1][0], bl[1][2]);
                MMA_F16(acc[0][3], ah[0], bl[1][1], bl[1][3]);
                MMA_F16(acc[1][3], ah[1], bl[1][1], bl[1][3]);
            }
        }
    }
}

// Fragment->(row,col): row = mw*32 + mt*16 + (lane>>2) + 8*h ;
// col = nwq*32 + nt*8 + (lane&3)*2 + {0,1}.

// ---------------- 0) converts -------------------------------------------------
__device__ __forceinline__ void split_store(float x, __half* hi,
                                            __half* lo, size_t i)
{
    __half h = __float2half_rn(x);
    hi[i] = h;
    lo[i] = __float2half_rn(x - __half2float(h));
}

__global__ void convert_x_kernel(const float* __restrict__ src) {
    const int i4 = blockIdx.x * 256 + threadIdx.x;
    const size_t i = (size_t)i4 * 4;
    if (i + 3 < (size_t)BS_ * D_) {
        float4 v = *(const float4*)(src + i);
        __half h0 = __float2half_rn(v.x), h1 = __float2half_rn(v.y);
        __half h2 = __float2half_rn(v.z), h3 = __float2half_rn(v.w);
        __half2 hp0 = __halves2half2(h0, h1), hp1 = __halves2half2(h2, h3);
        __half2 lp0 = __halves2half2(__float2half_rn(v.x - __half2float(h0)),
                                     __float2half_rn(v.y - __half2float(h1)));
        __half2 lp1 = __halves2half2(__float2half_rn(v.z - __half2float(h2)),
                                     __float2half_rn(v.w - __half2float(h3)));
        *(__half2*)(g_Xhi + i)     = hp0;
        *(__half2*)(g_Xhi + i + 2) = hp1;
        *(__half2*)(g_Xlo + i)     = lp0;
        *(__half2*)(g_Xlo + i + 2) = lp1;
    }
}

__global__ void convert_small_kernel(
    const float* __restrict__ w0, const float* __restrict__ w1,
    const float* __restrict__ w2, const float* __restrict__ w3,
    const float* __restrict__ r0, const float* __restrict__ r1)
{
    const int z = blockIdx.y;
    const float* src;
    __half *hi, *lo;
    int n;
    if (z < 4) {
        src = (z == 0) ? w0 : (z == 1) ? w1 : (z == 2) ? w2 : w3;
        hi = g_Whi[z]; lo = g_Wlo[z]; n = D_ * D_;
    } else {
        src = (z == 4) ? r0 : r1;
        hi = g_Rhi[z - 4]; lo = g_Rlo[z - 4]; n = NREL * D_;
    }
    int i = blockIdx.x * 256 + threadIdx.x;
    if (i < n) split_store(src[i], hi, lo, i);
}

// ---------------- 1) projections (full 3-MMA precision) ----------------------
// Q-lo (z=0,2) never consumed; K-lo (z=1,3) only consumed by qr? No: scores
// now reads only K-hi, but qr reads rel-lo, not K-lo. K-lo still needed? No!
// scores was the only consumer of K-lo. qr consumes rel_lo. So skip ALL P-lo
// stores except none... K-lo (z=1,3) was consumed by scores' 2-MMA path,
// which is now 1-MMA. Keep storing K-lo anyway? Not needed -> skip all lo.
__global__ void __launch_bounds__(256, 2)
proj_kernel(const float* __restrict__ bq1, const float* __restrict__ bk1,
            const float* __restrict__ bq2, const float* __restrict__ bk2)
{
    const int z = blockIdx.z;
    const float* bias = (z == 0) ? bq1 : (z == 1) ? bk1 : (z == 2) ? bq2 : bk2;
    const float scale = (z == 0 || z == 2) ? 0.0625f : 1.0f;

    const int mBase = blockIdx.y * 128;
    const int nBase = blockIdx.x * 128;

    float acc[2][8][4];
    gemm_mma3(g_Xhi, g_Xlo, g_Whi[z], g_Wlo[z], mBase, nBase, acc);

    const int lane = threadIdx.x & 31, wid = threadIdx.x >> 5;
    const int mw = wid >> 1, nw = wid & 1;

#pragma unroll
    for (int mt = 0; mt < 2; mt++) {
#pragma unroll
        for (int h = 0; h < 2; h++) {
            const int m = mBase + mw * 32 + mt * 16 + (lane >> 2) + 8 * h;
            __half* dhi = g_Phi[z] + (size_t)m * D_;
#pragma unroll
            for (int nt = 0; nt < 8; nt++) {
                const int col = nBase + nw * 64 + nt * 8 + (lane & 3) * 2;
                float y0 = (acc[mt][nt][h * 2 + 0] + bias[col + 0]) * scale;
                float y1 = (acc[mt][nt][h * 2 + 1] + bias[col + 1]) * scale;
                *(__half2*)(dhi + col) =
                    __halves2half2(__float2half_rn(y0), __float2half_rn(y1));
            }
        }
    }
}

// ---------------- 2) q_rel: cols 0..127 via GEMM (2-MMA, 512 thr) ------------
__global__ void __launch_bounds__(512, 2)
qr_kernel()
{
    const int head  = blockIdx.z;
    const int mBase = blockIdx.y * 128;

    float acc[2][4][4];
    gemm_mmaN<2, 3>(g_Phi[head * 2], g_Rhi[head], g_Rlo[head],
                    mBase, 0, 128, acc);

    const int lane = threadIdx.x & 31, wid = threadIdx.x >> 5;
    const int mw = wid >> 2, nwq = wid & 3;

#pragma unroll
    for (int mt = 0; mt < 2; mt++) {
#pragma unroll
        for (int h = 0; h < 2; h++) {
            const int m = mBase + mw * 32 + mt * 16 + (lane >> 2) + 8 * h;
            float* dst = g_QR[head] + (size_t)m * QRS;
#pragma unroll
            for (int nt = 0; nt < 4; nt++) {
                const int col = nwq * 32 + nt * 8 + (lane & 3) * 2;
                *(float2*)(dst + col) =
                    make_float2(acc[mt][nt][h * 2 + 0], acc[mt][nt][h * 2 + 1]);
            }
        }
    }
}

// ---------------- 2b) q_rel column 128 (rel position +64) via GEMV -----------
__global__ void __launch_bounds__(256)
qr_col_kernel()
{
    const int gw   = blockIdx.x * 8 + (threadIdx.x >> 5);  // 0..2047
    const int lane = threadIdx.x & 31;
    const int head = gw >> 10;
    const int row0 = (gw & 1023) * 16;

    float rf[8];
    {
        const __half* rh = g_Rhi[head] + (size_t)128 * D_ + lane * 8;
        const __half* rl = g_Rlo[head] + (size_t)128 * D_ + lane * 8;
        uint4 vh = *(const uint4*)rh;
        uint4 vl = *(const uint4*)rl;
        const __half* ph = (const __half*)&vh;
        const __half* pl = (const __half*)&vl;
#pragma unroll
        for (int j = 0; j < 8; j++)
            rf[j] = __half2float(ph[j]) + __half2float(pl[j]);
    }

    const __half* Qhi = g_Phi[head * 2];

    for (int r = 0; r < 16; r++) {
        const int row = row0 + r;
        uint4 vh = *(const uint4*)(Qhi + (size_t)row * D_ + lane * 8);
        const __half* ph = (const __half*)&vh;
        float s = 0.f;
#pragma unroll
        for (int j = 0; j < 8; j++)
            s += __half2float(ph[j]) * rf[j];
#pragma unroll
        for (int o = 16; o > 0; o >>= 1)
            s += __shfl_xor_sync(0xFFFFFFFF, s, o);
        if (lane == 0) g_QR[head][(size_t)row * QRS + 128] = s;
    }
}

// ---------------- 3) scores (1-MMA, 512 thr, 4 stages) -----------------------
__global__ void __launch_bounds__(512, 2)
scores_kernel(const int* __restrict__ mask, float* __restrict__ out)
{
    const int z    = blockIdx.z;
    const int head = z >> 3;
    const int b    = z & 7;
    const int qBase = blockIdx.y * 128;
    const int kBase = blockIdx.x * 128;

    const size_t po = (size_t)b * S_ * D_;
    float acc[2][4][4];
    gemm_mmaN<1, 4>(g_Phi[head * 2 + 0] + po,
                    g_Phi[head * 2 + 1] + po, nullptr,
                    qBase, kBase, 1 << 30, acc);

    const int lane = threadIdx.x & 31, wid = threadIdx.x >> 5;
    const int mw = wid >> 2, nwq = wid & 3;
    const int* mrow = mask + b * S_;

#pragma unroll
    for (int mt = 0; mt < 2; mt++) {
#pragma unroll
        for (int h = 0; h < 2; h++) {
            const int qg = qBase + mw * 32 + mt * 16 + (lane >> 2) + 8 * h;
            const int mq = mrow[qg];
            const float* qr = g_QR[head] + ((size_t)b * S_ + qg) * QRS;
            float* orow = out + (((size_t)head * B_ + b) * S_ + qg) * S_;
#pragma unroll
            for (int nt = 0; nt < 4; nt++) {
                const int kg = kBase + nwq * 32 + nt * 8 + (lane & 3) * 2;
                int d0 = kg - qg;
                int d1 = d0 + 1;
                d0 = (d0 < -64) ? -64 : ((d0 > 64) ? 64 : d0);
                d1 = (d1 < -64) ? -64 : ((d1 > 64) ? 64 : d1);
                float v0 = acc[mt][nt][h * 2 + 0] + qr[d0 + 64];
                float v1 = acc[mt][nt][h * 2 + 1] + qr[d1 + 64];
                if (mq == 0 || mrow[kg + 0] == 0) v0 = -1e18f;
                if (mq == 0 || mrow[kg + 1] == 0) v1 = -1e18f;
                float2 v = make_float2(v0, v1);
                *(float2*)(orow + kg) = v;
            }
        }
    }
}

// ---------------- launch --------------------------------------------------------
extern "C" void kernel_launch(void* const* d_in, const int* in_sizes, int n_in,
                              void* d_out, int out_size)
{
    const float* repre = (const float*)d_in[0];
    const int*   mask  = (const int*)d_in[1];
    const float* wq1 = (const float*)d_in[2];
    const float* bq1 = (const float*)d_in[3];
    const float* wk1 = (const float*)d_in[4];
    const float* bk1 = (const float*)d_in[5];
    const float* rel1 = (const float*)d_in[6];
    const float* wq2 = (const float*)d_in[7];
    const float* bq2 = (const float*)d_in[8];
    const float* wk2 = (const float*)d_in[9];
    const float* bk2 = (const float*)d_in[10];
    const float* rel2 = (const float*)d_in[11];
    float* out = (float*)d_out;
    (void)in_sizes; (void)n_in; (void)out_size;

    cudaFuncSetAttribute(proj_kernel,
                         cudaFuncAttributeMaxDynamicSharedMemorySize, SMEM4);
    cudaFuncSetAttribute(qr_kernel,
                         cudaFuncAttributeMaxDynamicSharedMemorySize, SMEM_QR);
    cudaFuncSetAttribute(scores_kernel,
                         cudaFuncAttributeMaxDynamicSharedMemorySize, SMEM_SC);

    const int NX4 = BS_ * D_ / 4;
    const int NW = D_ * D_;

    convert_x_kernel<<<(NX4 + 255) / 256, 256>>>(repre);
    convert_small_kernel<<<dim3((NW + 255) / 256, 6), 256>>>(
        wq1, wk1, wq2, wk2, rel1, rel2);

    proj_kernel<<<dim3(2, 128, 4), 256, SMEM4>>>(bq1, bk1, bq2, bk2);
    qr_kernel<<<dim3(1, 128, 2), 512, SMEM_QR>>>();
    qr_col_kernel<<<256, 256>>>();
    scores_kernel<<<dim3(16, 16, 16), 512, SMEM_SC>>>(mask, out);
}

// round 14
// speedup vs baseline: 1.4981x; 1.0992x over previous
#include <cuda_runtime.h>
#include <cuda_fp16.h>
#include <cstdint>

// ---------------------------------------------------------------------------
// SpanClassifier via portable mma.sync fp16-split GEMMs.
//   B=8, S=2048, D=256, NREL=129
// Round 14: proj drops the X_lo term (X_lo*W never computed; Q/K are rounded
// to fp16 afterwards anyway, so marginal error is only sqrt(2) on the 2^-11
// rounding). proj now IS the 2-MMA core: gemm_mmaN<2,3>(X_hi, W_hi, W_lo)
// with 512-thr CTAs / 4x4 warp grid -> occ doubles vs the old 256-thr core.
//   proj:       2 MMAs (hiX*hiW + hiX*loW)
//   qr:         2 MMAs (hiQ*hiR + hiQ*loR)
//   scores:     1 MMA  (hiQ*hiK)
// Expected rel_err ~4e-4 (was 2.9e-4), threshold 1e-3.
// ---------------------------------------------------------------------------

namespace {
constexpr int B_   = 8;
constexpr int S_   = 2048;
constexpr int D_   = 256;
constexpr int NREL = 129;
constexpr int QRS  = 132;
constexpr int BS_  = B_ * S_;   // 16384

constexpr int KC    = 32;                 // k-chunk (fp16 elems)
constexpr int NCH   = D_ / KC;            // 8
constexpr int STRB  = 80;                 // smem row stride bytes (64 data + 16 pad)
constexpr int TILE_B = 128 * STRB;        // 10240 bytes

// 2-MMA core: 3 tiles x 3 stages ; 1-MMA core: 2 tiles x 4 stages
constexpr int SMEM_3T = 3 * 3 * TILE_B;   // 92160
constexpr int SMEM_2T = 4 * 2 * TILE_B;   // 81920
}

// ---------------- scratch (device globals; no runtime allocation) ----------
__device__ __half g_Xhi[BS_ * D_];
__device__ __half g_Phi[4][BS_ * D_];
__device__ __half g_Whi[4][D_ * D_];
__device__ __half g_Wlo[4][D_ * D_];
__device__ __half g_Rhi[2][NREL * D_];
__device__ __half g_Rlo[2][NREL * D_];
__device__ float g_QR[2][BS_ * QRS];

// ---------------- PTX helpers ----------------------------------------------
__device__ __forceinline__ uint32_t smem_u32(const void* p) {
    uint32_t a;
    asm("{ .reg .u64 t; cvta.to.shared.u64 t, %1; cvt.u32.u64 %0, t; }"
        : "=r"(a) : "l"(p));
    return a;
}

#define LDSM4(R, addr)                                                        \
    asm volatile("ldmatrix.sync.aligned.m8n8.x4.shared.b16 {%0,%1,%2,%3}, [%4];" \
                 : "=r"((R)[0]), "=r"((R)[1]), "=r"((R)[2]), "=r"((R)[3])     \
                 : "r"(addr))

#define MMA_F16(C, A, B0, B1)                                                 \
    asm volatile("mma.sync.aligned.m16n8k16.row.col.f32.f16.f16.f32 "         \
                 "{%0,%1,%2,%3},{%4,%5,%6,%7},{%8,%9},{%0,%1,%2,%3};"         \
                 : "+f"((C)[0]), "+f"((C)[1]), "+f"((C)[2]), "+f"((C)[3])     \
                 : "r"((A)[0]), "r"((A)[1]), "r"((A)[2]), "r"((A)[3]),        \
                   "r"(B0), "r"(B1))

__device__ __forceinline__ void cp16(uint32_t dst, const void* src, bool valid) {
    uint32_t n = valid ? 16u : 0u;
    asm volatile("cp.async.cg.shared.global [%0], [%1], 16, %2;"
                 :: "r"(dst), "l"(src), "r"(n));
}
#define CP_COMMIT() asm volatile("cp.async.commit_group;" ::: "memory")
#define CP_WAIT(n)  asm volatile("cp.async.wait_group %0;" :: "n"(n) : "memory")

extern __shared__ char dynsm[];

// ============================================================================
//  Templated 1/2-MMA core: 512 threads, 4x4 warp grid, 32x32 warp tiles.
//  NMMA=2: tiles {A, BH, BL}, NSTAGE=3. NMMA=1: tiles {A, BH}, NSTAGE=4.
//  acc[2][4][4]: row = mw*32 + mt*16 + (lane>>2) + 8*h,
//                col = nwq*32 + nt*8 + (lane&3)*2 + {0,1}.
// ============================================================================
template <int NMMA>
__device__ __forceinline__ void prefetchN(
    uint32_t smstage,
    const __half* __restrict__ Ahi,
    const __half* __restrict__ Bhi, const __half* __restrict__ Blo,
    int rowA0, int rowB0, int bLim, int col0, int tid)
{
    const int r  = tid >> 2;          // 0..127
    const int c4 = tid & 3;
    const uint32_t so = (uint32_t)(r * STRB + c4 * 16);
    const size_t gao = (size_t)(rowA0 + r) * D_ + col0 + c4 * 8;
    cp16(smstage + so, Ahi + gao, true);
    const bool bv = (rowB0 + r) < bLim;
    const int gbr = bv ? (rowB0 + r) : 0;
    const size_t gbo = (size_t)gbr * D_ + col0 + c4 * 8;
    cp16(smstage + (uint32_t)TILE_B + so, Bhi + gbo, bv);
    if (NMMA == 2)
        cp16(smstage + (uint32_t)(2 * TILE_B) + so, Blo + gbo, bv);
}

template <int NMMA, int NSTAGE>
__device__ __forceinline__ void gemm_mmaN(
    const __half* __restrict__ Ahi,
    const __half* __restrict__ Bhi, const __half* __restrict__ Blo,
    int rowA0, int rowB0, int bLim, float acc[2][4][4])
{
    constexpr int STG_B = (1 + NMMA) * TILE_B;

    const int tid  = threadIdx.x;
    const int lane = tid & 31;
    const int wid  = tid >> 5;       // 0..15
    const int mw   = wid >> 2;       // 0..3
    const int nwq  = wid & 3;        // 0..3

    const uint32_t smb = smem_u32(dynsm);
    const int lrow       = lane & 15;
    const uint32_t khalf = (uint32_t)((lane >> 4) * 16);
    const uint32_t aOff = (uint32_t)((mw * 32 + lrow) * STRB) + khalf;
    const uint32_t bOff = (uint32_t)((nwq * 32 + lrow) * STRB) + khalf;

#pragma unroll
    for (int mt = 0; mt < 2; mt++)
#pragma unroll
        for (int nt = 0; nt < 4; nt++)
#pragma unroll
            for (int e = 0; e < 4; e++) acc[mt][nt][e] = 0.f;

    // prologue: NSTAGE-1 chunks in flight
#pragma unroll
    for (int s = 0; s < NSTAGE - 1; s++) {
        prefetchN<NMMA>(smb + s * STG_B, Ahi, Bhi, Blo,
                        rowA0, rowB0, bLim, s * KC, tid);
        CP_COMMIT();
    }

    int stage_c = 0;   // stage holding chunk c
    for (int c = 0; c < NCH; c++) {
        const int outst = NCH - 1 - c;
        if (NSTAGE == 4) {
            if (outst >= 2)      { CP_WAIT(2); }
            else if (outst == 1) { CP_WAIT(1); }
            else                 { CP_WAIT(0); }
        } else {
            if (outst >= 1)      { CP_WAIT(1); }
            else                 { CP_WAIT(0); }
        }
        __syncthreads();   // chunk c visible; all warps done with c-1

        if (c + NSTAGE - 1 < NCH) {
            int stage_n = stage_c + NSTAGE - 1;
            if (stage_n >= NSTAGE) stage_n -= NSTAGE;
            prefetchN<NMMA>(smb + stage_n * STG_B, Ahi, Bhi, Blo,
                            rowA0, rowB0, bLim, (c + NSTAGE - 1) * KC, tid);
            CP_COMMIT();
        }

        const uint32_t st = smb + stage_c * STG_B;
        if (++stage_c == NSTAGE) stage_c = 0;
        const uint32_t aB  = st + aOff;
        const uint32_t bhB = st + (uint32_t)TILE_B + bOff;

#pragma unroll
        for (int ks = 0; ks < 2; ks++) {
            const uint32_t ko = (uint32_t)(ks * 32);
            uint32_t ah[2][4], bh[2][4];
            LDSM4(ah[0], aB + ko);
            LDSM4(ah[1], aB + (uint32_t)(16 * STRB) + ko);
            LDSM4(bh[0], bhB + ko);
            LDSM4(bh[1], bhB + (uint32_t)(16 * STRB) + ko);
            // hh phase: 8 independent accumulators
            MMA_F16(acc[0][0], ah[0], bh[0][0], bh[0][2]);
            MMA_F16(acc[1][0], ah[1], bh[0][0], bh[0][2]);
            MMA_F16(acc[0][1], ah[0], bh[0][1], bh[0][3]);
            MMA_F16(acc[1][1], ah[1], bh[0][1], bh[0][3]);
            MMA_F16(acc[0][2], ah[0], bh[1][0], bh[1][2]);
            MMA_F16(acc[1][2], ah[1], bh[1][0], bh[1][2]);
            MMA_F16(acc[0][3], ah[0], bh[1][1], bh[1][3]);
            MMA_F16(acc[1][3], ah[1], bh[1][1], bh[1][3]);
            if (NMMA == 2) {
                uint32_t bl[2][4];
                LDSM4(bl[0], bhB + (uint32_t)TILE_B + ko);
                LDSM4(bl[1], bhB + (uint32_t)(TILE_B + 16 * STRB) + ko);
                MMA_F16(acc[0][0], ah[0], bl[0][0], bl[0][2]);
                MMA_F16(acc[1][0], ah[1], bl[0][0], bl[0][2]);
                MMA_F16(acc[0][1], ah[0], bl[0][1], bl[0][3]);
                MMA_F16(acc[1][1], ah[1], bl[0][1], bl[0][3]);
                MMA_F16(acc[0][2], ah[0], bl[1][0], bl[1][2]);
                MMA_F16(acc[1][2], ah[1], bl[1][0], bl[1][2]);
                MMA_F16(acc[0][3], ah[0], bl[1][1], bl[1][3]);
                MMA_F16(acc[1][3], ah[1], bl[1][1], bl[1][3]);
            }
        }
    }
}

// ---------------- 0) converts -------------------------------------------------
__device__ __forceinline__ void split_store(float x, __half* hi,
                                            __half* lo, size_t i)
{
    __half h = __float2half_rn(x);
    hi[i] = h;
    lo[i] = __float2half_rn(x - __half2float(h));
}

// X: hi only (lo term dropped from proj)
__global__ void convert_x_kernel(const float* __restrict__ src) {
    const int i4 = blockIdx.x * 256 + threadIdx.x;
    const size_t i = (size_t)i4 * 4;
    if (i + 3 < (size_t)BS_ * D_) {
        float4 v = *(const float4*)(src + i);
        __half2 hp0 = __halves2half2(__float2half_rn(v.x), __float2half_rn(v.y));
        __half2 hp1 = __halves2half2(__float2half_rn(v.z), __float2half_rn(v.w));
        *(__half2*)(g_Xhi + i)     = hp0;
        *(__half2*)(g_Xhi + i + 2) = hp1;
    }
}

__global__ void convert_small_kernel(
    const float* __restrict__ w0, const float* __restrict__ w1,
    const float* __restrict__ w2, const float* __restrict__ w3,
    const float* __restrict__ r0, const float* __restrict__ r1)
{
    const int z = blockIdx.y;
    const float* src;
    __half *hi, *lo;
    int n;
    if (z < 4) {
        src = (z == 0) ? w0 : (z == 1) ? w1 : (z == 2) ? w2 : w3;
        hi = g_Whi[z]; lo = g_Wlo[z]; n = D_ * D_;
    } else {
        src = (z == 4) ? r0 : r1;
        hi = g_Rhi[z - 4]; lo = g_Rlo[z - 4]; n = NREL * D_;
    }
    int i = blockIdx.x * 256 + threadIdx.x;
    if (i < n) split_store(src[i], hi, lo, i);
}

// ---------------- 1) projections (2-MMA, 512 thr) ----------------------------
__global__ void __launch_bounds__(512, 2)
proj_kernel(const float* __restrict__ bq1, const float* __restrict__ bk1,
            const float* __restrict__ bq2, const float* __restrict__ bk2)
{
    const int z = blockIdx.z;
    const float* bias = (z == 0) ? bq1 : (z == 1) ? bk1 : (z == 2) ? bq2 : bk2;
    const float scale = (z == 0 || z == 2) ? 0.0625f : 1.0f;

    const int mBase = blockIdx.y * 128;
    const int nBase = blockIdx.x * 128;

    float acc[2][4][4];
    gemm_mmaN<2, 3>(g_Xhi, g_Whi[z], g_Wlo[z], mBase, nBase, 1 << 30, acc);

    const int lane = threadIdx.x & 31, wid = threadIdx.x >> 5;
    const int mw = wid >> 2, nwq = wid & 3;

#pragma unroll
    for (int mt = 0; mt < 2; mt++) {
#pragma unroll
        for (int h = 0; h < 2; h++) {
            const int m = mBase + mw * 32 + mt * 16 + (lane >> 2) + 8 * h;
            __half* dhi = g_Phi[z] + (size_t)m * D_;
#pragma unroll
            for (int nt = 0; nt < 4; nt++) {
                const int col = nBase + nwq * 32 + nt * 8 + (lane & 3) * 2;
                float y0 = (acc[mt][nt][h * 2 + 0] + bias[col + 0]) * scale;
                float y1 = (acc[mt][nt][h * 2 + 1] + bias[col + 1]) * scale;
                *(__half2*)(dhi + col) =
                    __halves2half2(__float2half_rn(y0), __float2half_rn(y1));
            }
        }
    }
}

// ---------------- 2) q_rel: cols 0..127 via GEMM (2-MMA, 512 thr) ------------
__global__ void __launch_bounds__(512, 2)
qr_kernel()
{
    const int head  = blockIdx.z;
    const int mBase = blockIdx.y * 128;

    float acc[2][4][4];
    gemm_mmaN<2, 3>(g_Phi[head * 2], g_Rhi[head], g_Rlo[head],
                    mBase, 0, 128, acc);

    const int lane = threadIdx.x & 31, wid = threadIdx.x >> 5;
    const int mw = wid >> 2, nwq = wid & 3;

#pragma unroll
    for (int mt = 0; mt < 2; mt++) {
#pragma unroll
        for (int h = 0; h < 2; h++) {
            const int m = mBase + mw * 32 + mt * 16 + (lane >> 2) + 8 * h;
            float* dst = g_QR[head] + (size_t)m * QRS;
#pragma unroll
            for (int nt = 0; nt < 4; nt++) {
                const int col = nwq * 32 + nt * 8 + (lane & 3) * 2;
                *(float2*)(dst + col) =
                    make_float2(acc[mt][nt][h * 2 + 0], acc[mt][nt][h * 2 + 1]);
            }
        }
    }
}

// ---------------- 2b) q_rel column 128 (rel position +64) via GEMV -----------
__global__ void __launch_bounds__(256)
qr_col_kernel()
{
    const int gw   = blockIdx.x * 8 + (threadIdx.x >> 5);  // 0..2047
    const int lane = threadIdx.x & 31;
    const int head = gw >> 10;
    const int row0 = (gw & 1023) * 16;

    float rf[8];
    {
        const __half* rh = g_Rhi[head] + (size_t)128 * D_ + lane * 8;
        const __half* rl = g_Rlo[head] + (size_t)128 * D_ + lane * 8;
        uint4 vh = *(const uint4*)rh;
        uint4 vl = *(const uint4*)rl;
        const __half* ph = (const __half*)&vh;
        const __half* pl = (const __half*)&vl;
#pragma unroll
        for (int j = 0; j < 8; j++)
            rf[j] = __half2float(ph[j]) + __half2float(pl[j]);
    }

    const __half* Qhi = g_Phi[head * 2];

    for (int r = 0; r < 16; r++) {
        const int row = row0 + r;
        uint4 vh = *(const uint4*)(Qhi + (size_t)row * D_ + lane * 8);
        const __half* ph = (const __half*)&vh;
        float s = 0.f;
#pragma unroll
        for (int j = 0; j < 8; j++)
            s += __half2float(ph[j]) * rf[j];
#pragma unroll
        for (int o = 16; o > 0; o >>= 1)
            s += __shfl_xor_sync(0xFFFFFFFF, s, o);
        if (lane == 0) g_QR[head][(size_t)row * QRS + 128] = s;
    }
}

// ---------------- 3) scores (1-MMA, 512 thr, 4 stages) -----------------------
__global__ void __launch_bounds__(512, 2)
scores_kernel(const int* __restrict__ mask, float* __restrict__ out)
{
    const int z    = blockIdx.z;
    const int head = z >> 3;
    const int b    = z & 7;
    const int qBase = blockIdx.y * 128;
    const int kBase = blockIdx.x * 128;

    const size_t po = (size_t)b * S_ * D_;
    float acc[2][4][4];
    gemm_mmaN<1, 4>(g_Phi[head * 2 + 0] + po,
                    g_Phi[head * 2 + 1] + po, nullptr,
                    qBase, kBase, 1 << 30, acc);

    const int lane = threadIdx.x & 31, wid = threadIdx.x >> 5;
    const int mw = wid >> 2, nwq = wid & 3;
    const int* mrow = mask + b * S_;

#pragma unroll
    for (int mt = 0; mt < 2; mt++) {
#pragma unroll
        for (int h = 0; h < 2; h++) {
            const int qg = qBase + mw * 32 + mt * 16 + (lane >> 2) + 8 * h;
            const int mq = mrow[qg];
            const float* qr = g_QR[head] + ((size_t)b * S_ + qg) * QRS;
            float* orow = out + (((size_t)head * B_ + b) * S_ + qg) * S_;
#pragma unroll
            for (int nt = 0; nt < 4; nt++) {
                const int kg = kBase + nwq * 32 + nt * 8 + (lane & 3) * 2;
                int d0 = kg - qg;
                int d1 = d0 + 1;
                d0 = (d0 < -64) ? -64 : ((d0 > 64) ? 64 : d0);
                d1 = (d1 < -64) ? -64 : ((d1 > 64) ? 64 : d1);
                float v0 = acc[mt][nt][h * 2 + 0] + qr[d0 + 64];
                float v1 = acc[mt][nt][h * 2 + 1] + qr[d1 + 64];
                if (mq == 0 || mrow[kg + 0] == 0) v0 = -1e18f;
                if (mq == 0 || mrow[kg + 1] == 0) v1 = -1e18f;
                float2 v = make_float2(v0, v1);
                *(float2*)(orow + kg) = v;
            }
        }
    }
}

// ---------------- launch --------------------------------------------------------
extern "C" void kernel_launch(void* const* d_in, const int* in_sizes, int n_in,
                              void* d_out, int out_size)
{
    const float* repre = (const float*)d_in[0];
    const int*   mask  = (const int*)d_in[1];
    const float* wq1 = (const float*)d_in[2];
    const float* bq1 = (const float*)d_in[3];
    const float* wk1 = (const float*)d_in[4];
    const float* bk1 = (const float*)d_in[5];
    const float* rel1 = (const float*)d_in[6];
    const float* wq2 = (const float*)d_in[7];
    const float* bq2 = (const float*)d_in[8];
    const float* wk2 = (const float*)d_in[9];
    const float* bk2 = (const float*)d_in[10];
    const float* rel2 = (const float*)d_in[11];
    float* out = (float*)d_out;
    (void)in_sizes; (void)n_in; (void)out_size;

    cudaFuncSetAttribute(proj_kernel,
                         cudaFuncAttributeMaxDynamicSharedMemorySize, SMEM_3T);
    cudaFuncSetAttribute(qr_kernel,
                         cudaFuncAttributeMaxDynamicSharedMemorySize, SMEM_3T);
    cudaFuncSetAttribute(scores_kernel,
                         cudaFuncAttributeMaxDynamicSharedMemorySize, SMEM_2T);

    const int NX4 = BS_ * D_ / 4;
    const int NW = D_ * D_;

    convert_x_kernel<<<(NX4 + 255) / 256, 256>>>(repre);
    convert_small_kernel<<<dim3((NW + 255) / 256, 6), 256>>>(
        wq1, wk1, wq2, wk2, rel1, rel2);

    proj_kernel<<<dim3(2, 128, 4), 512, SMEM_3T>>>(bq1, bk1, bq2, bk2);
    qr_kernel<<<dim3(1, 128, 2), 512, SMEM_3T>>>();
    qr_col_kernel<<<256, 256>>>();
    scores_kernel<<<dim3(16, 16, 16), 512, SMEM_2T>>>(mask, out);
}

// round 15
// speedup vs baseline: 1.6625x; 1.1097x over previous
#include <cuda_runtime.h>
#include <cuda_fp16.h>
#include <cstdint>

// ---------------------------------------------------------------------------
// SpanClassifier via portable mma.sync fp16 GEMMs (single-MMA everywhere).
//   B=8, S=2048, D=256, NREL=129
// Round 15: all three GEMMs use ONE fp16 hi*hi MMA per k16 step.
// Calibrated error model: Q/K error sqrt(3)*2^-11 -> scores rel_err ~5.1e-4
// (measured 2.93e-4 @ sqrt(2)/sqrt(2) split in R13, 4.15e-4 @ +X_lo drop in
// R14; each dropped term multiplies by sqrt((n+1)/n)). qr's rel term is ~6%
// of score magnitude, so its lo-drop adds ~3e-5 (negligible).
// Core: 512-thr CTAs, 4x4 warp grid, 32x32 warp tiles, 2-tile stages,
// 4-stage cp.async pipeline, phase-independent MMA issue.
// ---------------------------------------------------------------------------

namespace {
constexpr int B_   = 8;
constexpr int S_   = 2048;
constexpr int D_   = 256;
constexpr int NREL = 129;
constexpr int QRS  = 132;
constexpr int BS_  = B_ * S_;   // 16384

constexpr int KC    = 32;                 // k-chunk (fp16 elems)
constexpr int NCH   = D_ / KC;            // 8
constexpr int STRB  = 80;                 // smem row stride bytes (64 data + 16 pad)
constexpr int TILE_B = 128 * STRB;        // 10240 bytes
constexpr int NSTAGE = 4;
constexpr int STG_B  = 2 * TILE_B;        // A + B tiles
constexpr int SMEM_DYN = NSTAGE * STG_B;  // 81920
}

// ---------------- scratch (device globals; no runtime allocation) ----------
__device__ __half g_Xhi[BS_ * D_];
__device__ __half g_Phi[4][BS_ * D_];
__device__ __half g_Whi[4][D_ * D_];
__device__ __half g_Rhi[2][NREL * D_];
__device__ float g_QR[2][BS_ * QRS];

// ---------------- PTX helpers ----------------------------------------------
__device__ __forceinline__ uint32_t smem_u32(const void* p) {
    uint32_t a;
    asm("{ .reg .u64 t; cvta.to.shared.u64 t, %1; cvt.u32.u64 %0, t; }"
        : "=r"(a) : "l"(p));
    return a;
}

#define LDSM4(R, addr)                                                        \
    asm volatile("ldmatrix.sync.aligned.m8n8.x4.shared.b16 {%0,%1,%2,%3}, [%4];" \
                 : "=r"((R)[0]), "=r"((R)[1]), "=r"((R)[2]), "=r"((R)[3])     \
                 : "r"(addr))

#define MMA_F16(C, A, B0, B1)                                                 \
    asm volatile("mma.sync.aligned.m16n8k16.row.col.f32.f16.f16.f32 "         \
                 "{%0,%1,%2,%3},{%4,%5,%6,%7},{%8,%9},{%0,%1,%2,%3};"         \
                 : "+f"((C)[0]), "+f"((C)[1]), "+f"((C)[2]), "+f"((C)[3])     \
                 : "r"((A)[0]), "r"((A)[1]), "r"((A)[2]), "r"((A)[3]),        \
                   "r"(B0), "r"(B1))

__device__ __forceinline__ void cp16(uint32_t dst, const void* src, bool valid) {
    uint32_t n = valid ? 16u : 0u;
    asm volatile("cp.async.cg.shared.global [%0], [%1], 16, %2;"
                 :: "r"(dst), "l"(src), "r"(n));
}
#define CP_COMMIT() asm volatile("cp.async.commit_group;" ::: "memory")
#define CP_WAIT(n)  asm volatile("cp.async.wait_group %0;" :: "n"(n) : "memory")

extern __shared__ char dynsm[];

// ============================================================================
//  1-MMA GEMM core: 512 threads, 4x4 warp grid, 32x32 warp tiles.
//  acc[2][4][4]: row = mw*32 + mt*16 + (lane>>2) + 8*h,
//                col = nwq*32 + nt*8 + (lane&3)*2 + {0,1}.
// ============================================================================
__device__ __forceinline__ void prefetch1(
    uint32_t smstage,
    const __half* __restrict__ A, const __half* __restrict__ Bm,
    int rowA0, int rowB0, int bLim, int col0, int tid)
{
    const int r  = tid >> 2;          // 0..127
    const int c4 = tid & 3;
    const uint32_t so = (uint32_t)(r * STRB + c4 * 16);
    const size_t gao = (size_t)(rowA0 + r) * D_ + col0 + c4 * 8;
    cp16(smstage + so, A + gao, true);
    const bool bv = (rowB0 + r) < bLim;
    const int gbr = bv ? (rowB0 + r) : 0;
    const size_t gbo = (size_t)gbr * D_ + col0 + c4 * 8;
    cp16(smstage + (uint32_t)TILE_B + so, Bm + gbo, bv);
}

__device__ __forceinline__ void gemm_core(
    const __half* __restrict__ A, const __half* __restrict__ Bm,
    int rowA0, int rowB0, int bLim, float acc[2][4][4])
{
    const int tid  = threadIdx.x;
    const int lane = tid & 31;
    const int wid  = tid >> 5;       // 0..15
    const int mw   = wid >> 2;       // 0..3
    const int nwq  = wid & 3;        // 0..3

    const uint32_t smb = smem_u32(dynsm);
    const int lrow       = lane & 15;
    const uint32_t khalf = (uint32_t)((lane >> 4) * 16);
    const uint32_t aOff = (uint32_t)((mw * 32 + lrow) * STRB) + khalf;
    const uint32_t bOff = (uint32_t)((nwq * 32 + lrow) * STRB) + khalf;

#pragma unroll
    for (int mt = 0; mt < 2; mt++)
#pragma unroll
        for (int nt = 0; nt < 4; nt++)
#pragma unroll
            for (int e = 0; e < 4; e++) acc[mt][nt][e] = 0.f;

    // prologue: NSTAGE-1 chunks in flight
#pragma unroll
    for (int s = 0; s < NSTAGE - 1; s++) {
        prefetch1(smb + s * STG_B, A, Bm, rowA0, rowB0, bLim, s * KC, tid);
        CP_COMMIT();
    }

    int stage_c = 0;   // stage holding chunk c
    for (int c = 0; c < NCH; c++) {
        const int outst = NCH - 1 - c;
        if (outst >= 2)      { CP_WAIT(2); }
        else if (outst == 1) { CP_WAIT(1); }
        else                 { CP_WAIT(0); }
        __syncthreads();   // chunk c visible; all warps done with c-1

        if (c + NSTAGE - 1 < NCH) {
            int stage_n = stage_c + NSTAGE - 1;
            if (stage_n >= NSTAGE) stage_n -= NSTAGE;
            prefetch1(smb + stage_n * STG_B, A, Bm,
                      rowA0, rowB0, bLim, (c + NSTAGE - 1) * KC, tid);
            CP_COMMIT();
        }

        const uint32_t st = smb + stage_c * STG_B;
        if (++stage_c == NSTAGE) stage_c = 0;
        const uint32_t aB  = st + aOff;
        const uint32_t bhB = st + (uint32_t)TILE_B + bOff;

#pragma unroll
        for (int ks = 0; ks < 2; ks++) {
            const uint32_t ko = (uint32_t)(ks * 32);
            uint32_t ah[2][4], bh[2][4];
            LDSM4(ah[0], aB + ko);
            LDSM4(ah[1], aB + (uint32_t)(16 * STRB) + ko);
            LDSM4(bh[0], bhB + ko);
            LDSM4(bh[1], bhB + (uint32_t)(16 * STRB) + ko);
            // 8 independent accumulators
            MMA_F16(acc[0][0], ah[0], bh[0][0], bh[0][2]);
            MMA_F16(acc[1][0], ah[1], bh[0][0], bh[0][2]);
            MMA_F16(acc[0][1], ah[0], bh[0][1], bh[0][3]);
            MMA_F16(acc[1][1], ah[1], bh[0][1], bh[0][3]);
            MMA_F16(acc[0][2], ah[0], bh[1][0], bh[1][2]);
            MMA_F16(acc[1][2], ah[1], bh[1][0], bh[1][2]);
            MMA_F16(acc[0][3], ah[0], bh[1][1], bh[1][3]);
            MMA_F16(acc[1][3], ah[1], bh[1][1], bh[1][3]);
        }
    }
}

// ---------------- 0) converts (hi only) ---------------------------------------
__global__ void convert_x_kernel(const float* __restrict__ src) {
    const int i4 = blockIdx.x * 256 + threadIdx.x;
    const size_t i = (size_t)i4 * 4;
    if (i + 3 < (size_t)BS_ * D_) {
        float4 v = *(const float4*)(src + i);
        *(__half2*)(g_Xhi + i) =
            __halves2half2(__float2half_rn(v.x), __float2half_rn(v.y));
        *(__half2*)(g_Xhi + i + 2) =
            __halves2half2(__float2half_rn(v.z), __float2half_rn(v.w));
    }
}

__global__ void convert_small_kernel(
    const float* __restrict__ w0, const float* __restrict__ w1,
    const float* __restrict__ w2, const float* __restrict__ w3,
    const float* __restrict__ r0, const float* __restrict__ r1)
{
    const int z = blockIdx.y;
    const float* src;
    __half* hi;
    int n;
    if (z < 4) {
        src = (z == 0) ? w0 : (z == 1) ? w1 : (z == 2) ? w2 : w3;
        hi = g_Whi[z]; n = D_ * D_;
    } else {
        src = (z == 4) ? r0 : r1;
        hi = g_Rhi[z - 4]; n = NREL * D_;
    }
    int i = blockIdx.x * 256 + threadIdx.x;
    if (i < n) hi[i] = __float2half_rn(src[i]);
}

// ---------------- 1) projections (1-MMA) --------------------------------------
__global__ void __launch_bounds__(512, 2)
proj_kernel(const float* __restrict__ bq1, const float* __restrict__ bk1,
            const float* __restrict__ bq2, const float* __restrict__ bk2)
{
    const int z = blockIdx.z;
    const float* bias = (z == 0) ? bq1 : (z == 1) ? bk1 : (z == 2) ? bq2 : bk2;
    const float scale = (z == 0 || z == 2) ? 0.0625f : 1.0f;

    const int mBase = blockIdx.y * 128;
    const int nBase = blockIdx.x * 128;

    float acc[2][4][4];
    gemm_core(g_Xhi, g_Whi[z] + (size_t)nBase * D_ - (size_t)nBase * D_,
              mBase, nBase, 1 << 30, acc);
    // (pointer math no-op kept simple: rowB0=nBase indexes W rows directly)

    const int lane = threadIdx.x & 31, wid = threadIdx.x >> 5;
    const int mw = wid >> 2, nwq = wid & 3;

#pragma unroll
    for (int mt = 0; mt < 2; mt++) {
#pragma unroll
        for (int h = 0; h < 2; h++) {
            const int m = mBase + mw * 32 + mt * 16 + (lane >> 2) + 8 * h;
            __half* dhi = g_Phi[z] + (size_t)m * D_;
#pragma unroll
            for (int nt = 0; nt < 4; nt++) {
                const int col = nBase + nwq * 32 + nt * 8 + (lane & 3) * 2;
                float y0 = (acc[mt][nt][h * 2 + 0] + bias[col + 0]) * scale;
                float y1 = (acc[mt][nt][h * 2 + 1] + bias[col + 1]) * scale;
                *(__half2*)(dhi + col) =
                    __halves2half2(__float2half_rn(y0), __float2half_rn(y1));
            }
        }
    }
}

// ---------------- 2) q_rel: cols 0..127 via GEMM (1-MMA) ----------------------
__global__ void __launch_bounds__(512, 2)
qr_kernel()
{
    const int head  = blockIdx.z;
    const int mBase = blockIdx.y * 128;

    float acc[2][4][4];
    gemm_core(g_Phi[head * 2], g_Rhi[head], mBase, 0, 128, acc);

    const int lane = threadIdx.x & 31, wid = threadIdx.x >> 5;
    const int mw = wid >> 2, nwq = wid & 3;

#pragma unroll
    for (int mt = 0; mt < 2; mt++) {
#pragma unroll
        for (int h = 0; h < 2; h++) {
            const int m = mBase + mw * 32 + mt * 16 + (lane >> 2) + 8 * h;
            float* dst = g_QR[head] + (size_t)m * QRS;
#pragma unroll
            for (int nt = 0; nt < 4; nt++) {
                const int col = nwq * 32 + nt * 8 + (lane & 3) * 2;
                *(float2*)(dst + col) =
                    make_float2(acc[mt][nt][h * 2 + 0], acc[mt][nt][h * 2 + 1]);
            }
        }
    }
}

// ---------------- 2b) q_rel column 128 via GEMV (f32 rel source) --------------
__global__ void __launch_bounds__(256)
qr_col_kernel(const float* __restrict__ rel1, const float* __restrict__ rel2)
{
    const int gw   = blockIdx.x * 8 + (threadIdx.x >> 5);  // 0..2047
    const int lane = threadIdx.x & 31;
    const int head = gw >> 10;
    const int row0 = (gw & 1023) * 16;

    const float* rel = (head == 0) ? rel1 : rel2;
    float rf[8];
    {
        const float* rrow = rel + (size_t)128 * D_ + lane * 8;
        float4 a = *(const float4*)(rrow + 0);
        float4 b = *(const float4*)(rrow + 4);
        rf[0] = a.x; rf[1] = a.y; rf[2] = a.z; rf[3] = a.w;
        rf[4] = b.x; rf[5] = b.y; rf[6] = b.z; rf[7] = b.w;
    }

    const __half* Qhi = g_Phi[head * 2];

    for (int r = 0; r < 16; r++) {
        const int row = row0 + r;
        uint4 vh = *(const uint4*)(Qhi + (size_t)row * D_ + lane * 8);
        const __half* ph = (const __half*)&vh;
        float s = 0.f;
#pragma unroll
        for (int j = 0; j < 8; j++)
            s += __half2float(ph[j]) * rf[j];
#pragma unroll
        for (int o = 16; o > 0; o >>= 1)
            s += __shfl_xor_sync(0xFFFFFFFF, s, o);
        if (lane == 0) g_QR[head][(size_t)row * QRS + 128] = s;
    }
}

// ---------------- 3) scores (1-MMA) -------------------------------------------
__global__ void __launch_bounds__(512, 2)
scores_kernel(const int* __restrict__ mask, float* __restrict__ out)
{
    const int z    = blockIdx.z;
    const int head = z >> 3;
    const int b    = z & 7;
    const int qBase = blockIdx.y * 128;
    const int kBase = blockIdx.x * 128;

    const size_t po = (size_t)b * S_ * D_;
    float acc[2][4][4];
    gemm_core(g_Phi[head * 2 + 0] + po, g_Phi[head * 2 + 1] + po,
              qBase, kBase, 1 << 30, acc);

    const int lane = threadIdx.x & 31, wid = threadIdx.x >> 5;
    const int mw = wid >> 2, nwq = wid & 3;
    const int* mrow = mask + b * S_;

#pragma unroll
    for (int mt = 0; mt < 2; mt++) {
#pragma unroll
        for (int h = 0; h < 2; h++) {
            const int qg = qBase + mw * 32 + mt * 16 + (lane >> 2) + 8 * h;
            const int mq = mrow[qg];
            const float* qr = g_QR[head] + ((size_t)b * S_ + qg) * QRS;
            float* orow = out + (((size_t)head * B_ + b) * S_ + qg) * S_;
#pragma unroll
            for (int nt = 0; nt < 4; nt++) {
                const int kg = kBase + nwq * 32 + nt * 8 + (lane & 3) * 2;
                int d0 = kg - qg;
                int d1 = d0 + 1;
                d0 = (d0 < -64) ? -64 : ((d0 > 64) ? 64 : d0);
                d1 = (d1 < -64) ? -64 : ((d1 > 64) ? 64 : d1);
                float v0 = acc[mt][nt][h * 2 + 0] + qr[d0 + 64];
                float v1 = acc[mt][nt][h * 2 + 1] + qr[d1 + 64];
                if (mq == 0 || mrow[kg + 0] == 0) v0 = -1e18f;
                if (mq == 0 || mrow[kg + 1] == 0) v1 = -1e18f;
                float2 v = make_float2(v0, v1);
                *(float2*)(orow + kg) = v;
            }
        }
    }
}

// ---------------- launch --------------------------------------------------------
extern "C" void kernel_launch(void* const* d_in, const int* in_sizes, int n_in,
                              void* d_out, int out_size)
{
    const float* repre = (const float*)d_in[0];
    const int*   mask  = (const int*)d_in[1];
    const float* wq1 = (const float*)d_in[2];
    const float* bq1 = (const float*)d_in[3];
    const float* wk1 = (const float*)d_in[4];
    const float* bk1 = (const float*)d_in[5];
    const float* rel1 = (const float*)d_in[6];
    const float* wq2 = (const float*)d_in[7];
    const float* bq2 = (const float*)d_in[8];
    const float* wk2 = (const float*)d_in[9];
    const float* bk2 = (const float*)d_in[10];
    const float* rel2 = (const float*)d_in[11];
    float* out = (float*)d_out;
    (void)in_sizes; (void)n_in; (void)out_size;

    cudaFuncSetAttribute(proj_kernel,
                         cudaFuncAttributeMaxDynamicSharedMemorySize, SMEM_DYN);
    cudaFuncSetAttribute(qr_kernel,
                         cudaFuncAttributeMaxDynamicSharedMemorySize, SMEM_DYN);
    cudaFuncSetAttribute(scores_kernel,
                         cudaFuncAttributeMaxDynamicSharedMemorySize, SMEM_DYN);

    const int NX4 = BS_ * D_ / 4;
    const int NW = D_ * D_;

    convert_x_kernel<<<(NX4 + 255) / 256, 256>>>(repre);
    convert_small_kernel<<<dim3((NW + 255) / 256, 6), 256>>>(
        wq1, wk1, wq2, wk2, rel1, rel2);

    proj_kernel<<<dim3(2, 128, 4), 512, SMEM_DYN>>>(bq1, bk1, bq2, bk2);
    qr_kernel<<<dim3(1, 128, 2), 512, SMEM_DYN>>>();
    qr_col_kernel<<<256, 256>>>(rel1, rel2);
    scores_kernel<<<dim3(16, 16, 16), 512, SMEM_DYN>>>(mask, out);
}

// round 16
// speedup vs baseline: 1.7661x; 1.0623x over previous
#include <cuda_runtime.h>
#include <cuda_fp16.h>
#include <cstdint>

// ---------------------------------------------------------------------------
// SpanClassifier via portable mma.sync fp16 GEMMs (single-MMA everywhere).
//   B=8, S=2048, D=256, NREL=129
// Round 16:
//  - proj fused into ONE GEMM: X[16384,256] @ W_cat[1024,256]^T (g_Whi is
//    already the concatenation), grid (8,128); z = blockIdx.x>>1.
//  - scores epilogue fast path for fully-clamped tiles (|kBase-qBase|>=256:
//    rel term is a single scalar per row) -- 210/256 of tiles.
//  - streaming stores (st.global.cs) for the 256 MB output (never re-read;
//    stops it evicting Q/K/QR from L2).
// Core: 512-thr CTAs, 4x4 warp grid, 32x32 warp tiles, 2-tile stages,
// 4-stage cp.async pipeline. rel_err ~5.1e-4 (calibrated, unchanged).
// ---------------------------------------------------------------------------

namespace {
constexpr int B_   = 8;
constexpr int S_   = 2048;
constexpr int D_   = 256;
constexpr int NREL = 129;
constexpr int QRS  = 132;
constexpr int BS_  = B_ * S_;   // 16384

constexpr int KC    = 32;                 // k-chunk (fp16 elems)
constexpr int NCH   = D_ / KC;            // 8
constexpr int STRB  = 80;                 // smem row stride bytes (64 data + 16 pad)
constexpr int TILE_B = 128 * STRB;        // 10240 bytes
constexpr int NSTAGE = 4;
constexpr int STG_B  = 2 * TILE_B;        // A + B tiles
constexpr int SMEM_DYN = NSTAGE * STG_B;  // 81920
}

// ---------------- scratch (device globals; no runtime allocation) ----------
__device__ __half g_Xhi[BS_ * D_];
__device__ __half g_Phi[4][BS_ * D_];
__device__ __half g_Whi[4][D_ * D_];     // contiguous => W_cat[1024,256]
__device__ __half g_Rhi[2][NREL * D_];
__device__ float g_QR[2][BS_ * QRS];

// ---------------- PTX helpers ----------------------------------------------
__device__ __forceinline__ uint32_t smem_u32(const void* p) {
    uint32_t a;
    asm("{ .reg .u64 t; cvta.to.shared.u64 t, %1; cvt.u32.u64 %0, t; }"
        : "=r"(a) : "l"(p));
    return a;
}

#define LDSM4(R, addr)                                                        \
    asm volatile("ldmatrix.sync.aligned.m8n8.x4.shared.b16 {%0,%1,%2,%3}, [%4];" \
                 : "=r"((R)[0]), "=r"((R)[1]), "=r"((R)[2]), "=r"((R)[3])     \
                 : "r"(addr))

#define MMA_F16(C, A, B0, B1)                                                 \
    asm volatile("mma.sync.aligned.m16n8k16.row.col.f32.f16.f16.f32 "         \
                 "{%0,%1,%2,%3},{%4,%5,%6,%7},{%8,%9},{%0,%1,%2,%3};"         \
                 : "+f"((C)[0]), "+f"((C)[1]), "+f"((C)[2]), "+f"((C)[3])     \
                 : "r"((A)[0]), "r"((A)[1]), "r"((A)[2]), "r"((A)[3]),        \
                   "r"(B0), "r"(B1))

__device__ __forceinline__ void cp16(uint32_t dst, const void* src, bool valid) {
    uint32_t n = valid ? 16u : 0u;
    asm volatile("cp.async.cg.shared.global [%0], [%1], 16, %2;"
                 :: "r"(dst), "l"(src), "r"(n));
}
#define CP_COMMIT() asm volatile("cp.async.commit_group;" ::: "memory")
#define CP_WAIT(n)  asm volatile("cp.async.wait_group %0;" :: "n"(n) : "memory")

__device__ __forceinline__ void stcs2(float* p, float2 v) {
    asm volatile("st.global.cs.v2.f32 [%0], {%1, %2};"
                 :: "l"(p), "f"(v.x), "f"(v.y) : "memory");
}

extern __shared__ char dynsm[];

// ============================================================================
//  1-MMA GEMM core: 512 threads, 4x4 warp grid, 32x32 warp tiles.
//  acc[2][4][4]: row = mw*32 + mt*16 + (lane>>2) + 8*h,
//                col = nwq*32 + nt*8 + (lane&3)*2 + {0,1}.
// ============================================================================
__device__ __forceinline__ void prefetch1(
    uint32_t smstage,
    const __half* __restrict__ A, const __half* __restrict__ Bm,
    int rowA0, int rowB0, int bLim, int col0, int tid)
{
    const int r  = tid >> 2;          // 0..127
    const int c4 = tid & 3;
    const uint32_t so = (uint32_t)(r * STRB + c4 * 16);
    const size_t gao = (size_t)(rowA0 + r) * D_ + col0 + c4 * 8;
    cp16(smstage + so, A + gao, true);
    const bool bv = (rowB0 + r) < bLim;
    const int gbr = bv ? (rowB0 + r) : 0;
    const size_t gbo = (size_t)gbr * D_ + col0 + c4 * 8;
    cp16(smstage + (uint32_t)TILE_B + so, Bm + gbo, bv);
}

__device__ __forceinline__ void gemm_core(
    const __half* __restrict__ A, const __half* __restrict__ Bm,
    int rowA0, int rowB0, int bLim, float acc[2][4][4])
{
    const int tid  = threadIdx.x;
    const int lane = tid & 31;
    const int wid  = tid >> 5;       // 0..15
    const int mw   = wid >> 2;       // 0..3
    const int nwq  = wid & 3;        // 0..3

    const uint32_t smb = smem_u32(dynsm);
    const int lrow       = lane & 15;
    const uint32_t khalf = (uint32_t)((lane >> 4) * 16);
    const uint32_t aOff = (uint32_t)((mw * 32 + lrow) * STRB) + khalf;
    const uint32_t bOff = (uint32_t)((nwq * 32 + lrow) * STRB) + khalf;

#pragma unroll
    for (int mt = 0; mt < 2; mt++)
#pragma unroll
        for (int nt = 0; nt < 4; nt++)
#pragma unroll
            for (int e = 0; e < 4; e++) acc[mt][nt][e] = 0.f;

#pragma unroll
    for (int s = 0; s < NSTAGE - 1; s++) {
        prefetch1(smb + s * STG_B, A, Bm, rowA0, rowB0, bLim, s * KC, tid);
        CP_COMMIT();
    }

    int stage_c = 0;
    for (int c = 0; c < NCH; c++) {
        const int outst = NCH - 1 - c;
        if (outst >= 2)      { CP_WAIT(2); }
        else if (outst == 1) { CP_WAIT(1); }
        else                 { CP_WAIT(0); }
        __syncthreads();

        if (c + NSTAGE - 1 < NCH) {
            int stage_n = stage_c + NSTAGE - 1;
            if (stage_n >= NSTAGE) stage_n -= NSTAGE;
            prefetch1(smb + stage_n * STG_B, A, Bm,
                      rowA0, rowB0, bLim, (c + NSTAGE - 1) * KC, tid);
            CP_COMMIT();
        }

        const uint32_t st = smb + stage_c * STG_B;
        if (++stage_c == NSTAGE) stage_c = 0;
        const uint32_t aB  = st + aOff;
        const uint32_t bhB = st + (uint32_t)TILE_B + bOff;

#pragma unroll
        for (int ks = 0; ks < 2; ks++) {
            const uint32_t ko = (uint32_t)(ks * 32);
            uint32_t ah[2][4], bh[2][4];
            LDSM4(ah[0], aB + ko);
            LDSM4(ah[1], aB + (uint32_t)(16 * STRB) + ko);
            LDSM4(bh[0], bhB + ko);
            LDSM4(bh[1], bhB + (uint32_t)(16 * STRB) + ko);
            MMA_F16(acc[0][0], ah[0], bh[0][0], bh[0][2]);
            MMA_F16(acc[1][0], ah[1], bh[0][0], bh[0][2]);
            MMA_F16(acc[0][1], ah[0], bh[0][1], bh[0][3]);
            MMA_F16(acc[1][1], ah[1], bh[0][1], bh[0][3]);
            MMA_F16(acc[0][2], ah[0], bh[1][0], bh[1][2]);
            MMA_F16(acc[1][2], ah[1], bh[1][0], bh[1][2]);
            MMA_F16(acc[0][3], ah[0], bh[1][1], bh[1][3]);
            MMA_F16(acc[1][3], ah[1], bh[1][1], bh[1][3]);
        }
    }
}

// ---------------- 0) converts (hi only) ---------------------------------------
__global__ void convert_x_kernel(const float* __restrict__ src) {
    const int i4 = blockIdx.x * 256 + threadIdx.x;
    const size_t i = (size_t)i4 * 4;
    if (i + 3 < (size_t)BS_ * D_) {
        float4 v = *(const float4*)(src + i);
        *(__half2*)(g_Xhi + i) =
            __halves2half2(__float2half_rn(v.x), __float2half_rn(v.y));
        *(__half2*)(g_Xhi + i + 2) =
            __halves2half2(__float2half_rn(v.z), __float2half_rn(v.w));
    }
}

__global__ void convert_small_kernel(
    const float* __restrict__ w0, const float* __restrict__ w1,
    const float* __restrict__ w2, const float* __restrict__ w3,
    const float* __restrict__ r0, const float* __restrict__ r1)
{
    const int z = blockIdx.y;
    const float* src;
    __half* hi;
    int n;
    if (z < 4) {
        src = (z == 0) ? w0 : (z == 1) ? w1 : (z == 2) ? w2 : w3;
        hi = g_Whi[z]; n = D_ * D_;
    } else {
        src = (z == 4) ? r0 : r1;
        hi = g_Rhi[z - 4]; n = NREL * D_;
    }
    int i = blockIdx.x * 256 + threadIdx.x;
    if (i < n) hi[i] = __float2half_rn(src[i]);
}

// ---------------- 1) projections: ONE fused GEMM over W_cat[1024,256] --------
__global__ void __launch_bounds__(512, 2)
proj_kernel(const float* __restrict__ bq1, const float* __restrict__ bk1,
            const float* __restrict__ bq2, const float* __restrict__ bk2)
{
    const int mBase = blockIdx.y * 128;
    const int nBase = blockIdx.x * 128;      // 0..896, global W_cat row
    const int z = nBase >> 8;                // which of the 4 projections
    const int nLoc = nBase & 255;            // column base within that proj
    const float* bias = (z == 0) ? bq1 : (z == 1) ? bk1 : (z == 2) ? bq2 : bk2;
    const float scale = (z == 0 || z == 2) ? 0.0625f : 1.0f;

    float acc[2][4][4];
    gemm_core(g_Xhi, g_Whi[0], mBase, nBase, 1 << 30, acc);

    const int lane = threadIdx.x & 31, wid = threadIdx.x >> 5;
    const int mw = wid >> 2, nwq = wid & 3;

#pragma unroll
    for (int mt = 0; mt < 2; mt++) {
#pragma unroll
        for (int h = 0; h < 2; h++) {
            const int m = mBase + mw * 32 + mt * 16 + (lane >> 2) + 8 * h;
            __half* dhi = g_Phi[z] + (size_t)m * D_;
#pragma unroll
            for (int nt = 0; nt < 4; nt++) {
                const int col = nLoc + nwq * 32 + nt * 8 + (lane & 3) * 2;
                float y0 = (acc[mt][nt][h * 2 + 0] + bias[col + 0]) * scale;
                float y1 = (acc[mt][nt][h * 2 + 1] + bias[col + 1]) * scale;
                *(__half2*)(dhi + col) =
                    __halves2half2(__float2half_rn(y0), __float2half_rn(y1));
            }
        }
    }
}

// ---------------- 2) q_rel: cols 0..127 via GEMM (1-MMA) ----------------------
__global__ void __launch_bounds__(512, 2)
qr_kernel()
{
    const int head  = blockIdx.z;
    const int mBase = blockIdx.y * 128;

    float acc[2][4][4];
    gemm_core(g_Phi[head * 2], g_Rhi[head], mBase, 0, 128, acc);

    const int lane = threadIdx.x & 31, wid = threadIdx.x >> 5;
    const int mw = wid >> 2, nwq = wid & 3;

#pragma unroll
    for (int mt = 0; mt < 2; mt++) {
#pragma unroll
        for (int h = 0; h < 2; h++) {
            const int m = mBase + mw * 32 + mt * 16 + (lane >> 2) + 8 * h;
            float* dst = g_QR[head] + (size_t)m * QRS;
#pragma unroll
            for (int nt = 0; nt < 4; nt++) {
                const int col = nwq * 32 + nt * 8 + (lane & 3) * 2;
                *(float2*)(dst + col) =
                    make_float2(acc[mt][nt][h * 2 + 0], acc[mt][nt][h * 2 + 1]);
            }
        }
    }
}

// ---------------- 2b) q_rel column 128 via GEMV (f32 rel source) --------------
__global__ void __launch_bounds__(256)
qr_col_kernel(const float* __restrict__ rel1, const float* __restrict__ rel2)
{
    const int gw   = blockIdx.x * 8 + (threadIdx.x >> 5);  // 0..2047
    const int lane = threadIdx.x & 31;
    const int head = gw >> 10;
    const int row0 = (gw & 1023) * 16;

    const float* rel = (head == 0) ? rel1 : rel2;
    float rf[8];
    {
        const float* rrow = rel + (size_t)128 * D_ + lane * 8;
        float4 a = *(const float4*)(rrow + 0);
        float4 b = *(const float4*)(rrow + 4);
        rf[0] = a.x; rf[1] = a.y; rf[2] = a.z; rf[3] = a.w;
        rf[4] = b.x; rf[5] = b.y; rf[6] = b.z; rf[7] = b.w;
    }

    const __half* Qhi = g_Phi[head * 2];

    for (int r = 0; r < 16; r++) {
        const int row = row0 + r;
        uint4 vh = *(const uint4*)(Qhi + (size_t)row * D_ + lane * 8);
        const __half* ph = (const __half*)&vh;
        float s = 0.f;
#pragma unroll
        for (int j = 0; j < 8; j++)
            s += __half2float(ph[j]) * rf[j];
#pragma unroll
        for (int o = 16; o > 0; o >>= 1)
            s += __shfl_xor_sync(0xFFFFFFFF, s, o);
        if (lane == 0) g_QR[head][(size_t)row * QRS + 128] = s;
    }
}

// ---------------- 3) scores (1-MMA, fast/slow epilogue, streaming stores) ----
__global__ void __launch_bounds__(512, 2)
scores_kernel(const int* __restrict__ mask, float* __restrict__ out)
{
    const int z    = blockIdx.z;
    const int head = z >> 3;
    const int b    = z & 7;
    const int qBase = blockIdx.y * 128;
    const int kBase = blockIdx.x * 128;

    const size_t po = (size_t)b * S_ * D_;
    float acc[2][4][4];
    gemm_core(g_Phi[head * 2 + 0] + po, g_Phi[head * 2 + 1] + po,
              qBase, kBase, 1 << 30, acc);

    const int lane = threadIdx.x & 31, wid = threadIdx.x >> 5;
    const int mw = wid >> 2, nwq = wid & 3;
    const int* mrow = mask + b * S_;

    const int dTile = kBase - qBase;
    // Fully clamped tile: all d >= 64 (dTile >= 256) or all d <= -64 (<= -256)
    const bool fastPath = (dTile >= 256) || (dTile <= -256);
    const int clampIdx = (dTile >= 256) ? 128 : 0;   // qr column if clamped

#pragma unroll
    for (int mt = 0; mt < 2; mt++) {
#pragma unroll
        for (int h = 0; h < 2; h++) {
            const int qg = qBase + mw * 32 + mt * 16 + (lane >> 2) + 8 * h;
            const int mq = mrow[qg];
            const float* qr = g_QR[head] + ((size_t)b * S_ + qg) * QRS;
            float* orow = out + (((size_t)head * B_ + b) * S_ + qg) * S_;
            if (fastPath) {
                const float rc = qr[clampIdx];
#pragma unroll
                for (int nt = 0; nt < 4; nt++) {
                    const int kg = kBase + nwq * 32 + nt * 8 + (lane & 3) * 2;
                    float v0 = acc[mt][nt][h * 2 + 0] + rc;
                    float v1 = acc[mt][nt][h * 2 + 1] + rc;
                    if (mq == 0 || mrow[kg + 0] == 0) v0 = -1e18f;
                    if (mq == 0 || mrow[kg + 1] == 0) v1 = -1e18f;
                    stcs2(orow + kg, make_float2(v0, v1));
                }
            } else {
#pragma unroll
                for (int nt = 0; nt < 4; nt++) {
                    const int kg = kBase + nwq * 32 + nt * 8 + (lane & 3) * 2;
                    int d0 = kg - qg;
                    int d1 = d0 + 1;
                    d0 = (d0 < -64) ? -64 : ((d0 > 64) ? 64 : d0);
                    d1 = (d1 < -64) ? -64 : ((d1 > 64) ? 64 : d1);
                    float v0 = acc[mt][nt][h * 2 + 0] + qr[d0 + 64];
                    float v1 = acc[mt][nt][h * 2 + 1] + qr[d1 + 64];
                    if (mq == 0 || mrow[kg + 0] == 0) v0 = -1e18f;
                    if (mq == 0 || mrow[kg + 1] == 0) v1 = -1e18f;
                    stcs2(orow + kg, make_float2(v0, v1));
                }
            }
        }
    }
}

// ---------------- launch --------------------------------------------------------
extern "C" void kernel_launch(void* const* d_in, const int* in_sizes, int n_in,
                              void* d_out, int out_size)
{
    const float* repre = (const float*)d_in[0];
    const int*   mask  = (const int*)d_in[1];
    const float* wq1 = (const float*)d_in[2];
    const float* bq1 = (const float*)d_in[3];
    const float* wk1 = (const float*)d_in[4];
    const float* bk1 = (const float*)d_in[5];
    const float* rel1 = (const float*)d_in[6];
    const float* wq2 = (const float*)d_in[7];
    const float* bq2 = (const float*)d_in[8];
    const float* wk2 = (const float*)d_in[9];
    const float* bk2 = (const float*)d_in[10];
    const float* rel2 = (const float*)d_in[11];
    float* out = (float*)d_out;
    (void)in_sizes; (void)n_in; (void)out_size;

    cudaFuncSetAttribute(proj_kernel,
                         cudaFuncAttributeMaxDynamicSharedMemorySize, SMEM_DYN);
    cudaFuncSetAttribute(qr_kernel,
                         cudaFuncAttributeMaxDynamicSharedMemorySize, SMEM_DYN);
    cudaFuncSetAttribute(scores_kernel,
                         cudaFuncAttributeMaxDynamicSharedMemorySize, SMEM_DYN);

    const int NX4 = BS_ * D_ / 4;
    const int NW = D_ * D_;

    convert_x_kernel<<<(NX4 + 255) / 256, 256>>>(repre);
    convert_small_kernel<<<dim3((NW + 255) / 256, 6), 256>>>(
        wq1, wk1, wq2, wk2, rel1, rel2);

    proj_kernel<<<dim3(8, 128), 512, SMEM_DYN>>>(bq1, bk1, bq2, bk2);
    qr_kernel<<<dim3(1, 128, 2), 512, SMEM_DYN>>>();
    qr_col_kernel<<<256, 256>>>(rel1, rel2);
    scores_kernel<<<dim3(16, 16, 16), 512, SMEM_DYN>>>(mask, out);
}

// round 17
// speedup vs baseline: 1.8622x; 1.0544x over previous
#include <cuda_runtime.h>
#include <cuda_fp16.h>
#include <cstdint>

// ---------------------------------------------------------------------------
// SpanClassifier via portable mma.sync fp16 GEMMs (single-MMA everywhere).
//   B=8, S=2048, D=256, NREL=129
// Round 17: KC 32 -> 64 (NCH 8 -> 4): halves per-tile barrier count and loop
// overhead, the measured idle-issue-slot source. 3-stage pipeline of 36 KB
// stages (A+B, 128 rows x 144 B) = 108 KB/CTA, still 2 CTAs/SM.
// Everything else as R16: fused proj GEMM, scores fast-path epilogue,
// streaming stores, 512-thr CTAs, 4x4 warp grid, 32x32 warp tiles.
// rel_err ~5.1e-4 (numerics unchanged).
// ---------------------------------------------------------------------------

namespace {
constexpr int B_   = 8;
constexpr int S_   = 2048;
constexpr int D_   = 256;
constexpr int NREL = 129;
constexpr int QRS  = 132;
constexpr int BS_  = B_ * S_;   // 16384

constexpr int KC    = 64;                 // k-chunk (fp16 elems)
constexpr int NCH   = D_ / KC;            // 4
constexpr int STRB  = 144;                // smem row stride bytes (128 data + 16 pad)
constexpr int TILE_B = 128 * STRB;        // 18432 bytes
constexpr int NSTAGE = 3;
constexpr int STG_B  = 2 * TILE_B;        // A + B tiles = 36864
constexpr int SMEM_DYN = NSTAGE * STG_B;  // 110592
}

// ---------------- scratch (device globals; no runtime allocation) ----------
__device__ __half g_Xhi[BS_ * D_];
__device__ __half g_Phi[4][BS_ * D_];
__device__ __half g_Whi[4][D_ * D_];     // contiguous => W_cat[1024,256]
__device__ __half g_Rhi[2][NREL * D_];
__device__ float g_QR[2][BS_ * QRS];

// ---------------- PTX helpers ----------------------------------------------
__device__ __forceinline__ uint32_t smem_u32(const void* p) {
    uint32_t a;
    asm("{ .reg .u64 t; cvta.to.shared.u64 t, %1; cvt.u32.u64 %0, t; }"
        : "=r"(a) : "l"(p));
    return a;
}

#define LDSM4(R, addr)                                                        \
    asm volatile("ldmatrix.sync.aligned.m8n8.x4.shared.b16 {%0,%1,%2,%3}, [%4];" \
                 : "=r"((R)[0]), "=r"((R)[1]), "=r"((R)[2]), "=r"((R)[3])     \
                 : "r"(addr))

#define MMA_F16(C, A, B0, B1)                                                 \
    asm volatile("mma.sync.aligned.m16n8k16.row.col.f32.f16.f16.f32 "         \
                 "{%0,%1,%2,%3},{%4,%5,%6,%7},{%8,%9},{%0,%1,%2,%3};"         \
                 : "+f"((C)[0]), "+f"((C)[1]), "+f"((C)[2]), "+f"((C)[3])     \
                 : "r"((A)[0]), "r"((A)[1]), "r"((A)[2]), "r"((A)[3]),        \
                   "r"(B0), "r"(B1))

__device__ __forceinline__ void cp16(uint32_t dst, const void* src, bool valid) {
    uint32_t n = valid ? 16u : 0u;
    asm volatile("cp.async.cg.shared.global [%0], [%1], 16, %2;"
                 :: "r"(dst), "l"(src), "r"(n));
}
#define CP_COMMIT() asm volatile("cp.async.commit_group;" ::: "memory")
#define CP_WAIT(n)  asm volatile("cp.async.wait_group %0;" :: "n"(n) : "memory")

__device__ __forceinline__ void stcs2(float* p, float2 v) {
    asm volatile("st.global.cs.v2.f32 [%0], {%1, %2};"
                 :: "l"(p), "f"(v.x), "f"(v.y) : "memory");
}

extern __shared__ char dynsm[];

// ============================================================================
//  1-MMA GEMM core: 512 threads, 4x4 warp grid, 32x32 warp tiles, KC=64.
//  acc[2][4][4]: row = mw*32 + mt*16 + (lane>>2) + 8*h,
//                col = nwq*32 + nt*8 + (lane&3)*2 + {0,1}.
// ============================================================================
__device__ __forceinline__ void prefetch1(
    uint32_t smstage,
    const __half* __restrict__ A, const __half* __restrict__ Bm,
    int rowA0, int rowB0, int bLim, int col0, int tid)
{
#pragma unroll
    for (int t = 0; t < 2; t++) {
        const int idx = t * 512 + tid;    // 0..1023
        const int r   = idx >> 3;         // 0..127
        const int c8  = idx & 7;          // 16B group within 128B row
        const uint32_t so = (uint32_t)(r * STRB + c8 * 16);
        const size_t gao = (size_t)(rowA0 + r) * D_ + col0 + c8 * 8;
        cp16(smstage + so, A + gao, true);
        const bool bv = (rowB0 + r) < bLim;
        const int gbr = bv ? (rowB0 + r) : 0;
        const size_t gbo = (size_t)gbr * D_ + col0 + c8 * 8;
        cp16(smstage + (uint32_t)TILE_B + so, Bm + gbo, bv);
    }
}

__device__ __forceinline__ void gemm_core(
    const __half* __restrict__ A, const __half* __restrict__ Bm,
    int rowA0, int rowB0, int bLim, float acc[2][4][4])
{
    const int tid  = threadIdx.x;
    const int lane = tid & 31;
    const int wid  = tid >> 5;       // 0..15
    const int mw   = wid >> 2;       // 0..3
    const int nwq  = wid & 3;        // 0..3

    const uint32_t smb = smem_u32(dynsm);
    const int lrow       = lane & 15;
    const uint32_t khalf = (uint32_t)((lane >> 4) * 16);
    const uint32_t aOff = (uint32_t)((mw * 32 + lrow) * STRB) + khalf;
    const uint32_t bOff = (uint32_t)((nwq * 32 + lrow) * STRB) + khalf;

#pragma unroll
    for (int mt = 0; mt < 2; mt++)
#pragma unroll
        for (int nt = 0; nt < 4; nt++)
#pragma unroll
            for (int e = 0; e < 4; e++) acc[mt][nt][e] = 0.f;

#pragma unroll
    for (int s = 0; s < NSTAGE - 1; s++) {
        prefetch1(smb + s * STG_B, A, Bm, rowA0, rowB0, bLim, s * KC, tid);
        CP_COMMIT();
    }

    int stage_c = 0;
    for (int c = 0; c < NCH; c++) {
        const int outst = NCH - 1 - c;
        if (outst >= 1) { CP_WAIT(1); } else { CP_WAIT(0); }
        __syncthreads();   // chunk c visible; all warps done with c-1

        if (c + NSTAGE - 1 < NCH) {
            int stage_n = stage_c + NSTAGE - 1;
            if (stage_n >= NSTAGE) stage_n -= NSTAGE;
            prefetch1(smb + stage_n * STG_B, A, Bm,
                      rowA0, rowB0, bLim, (c + NSTAGE - 1) * KC, tid);
            CP_COMMIT();
        }

        const uint32_t st = smb + stage_c * STG_B;
        if (++stage_c == NSTAGE) stage_c = 0;
        const uint32_t aB  = st + aOff;
        const uint32_t bhB = st + (uint32_t)TILE_B + bOff;

#pragma unroll
        for (int ks = 0; ks < 4; ks++) {
            const uint32_t ko = (uint32_t)(ks * 32);
            uint32_t ah[2][4], bh[2][4];
            LDSM4(ah[0], aB + ko);
            LDSM4(ah[1], aB + (uint32_t)(16 * STRB) + ko);
            LDSM4(bh[0], bhB + ko);
            LDSM4(bh[1], bhB + (uint32_t)(16 * STRB) + ko);
            MMA_F16(acc[0][0], ah[0], bh[0][0], bh[0][2]);
            MMA_F16(acc[1][0], ah[1], bh[0][0], bh[0][2]);
            MMA_F16(acc[0][1], ah[0], bh[0][1], bh[0][3]);
            MMA_F16(acc[1][1], ah[1], bh[0][1], bh[0][3]);
            MMA_F16(acc[0][2], ah[0], bh[1][0], bh[1][2]);
            MMA_F16(acc[1][2], ah[1], bh[1][0], bh[1][2]);
            MMA_F16(acc[0][3], ah[0], bh[1][1], bh[1][3]);
            MMA_F16(acc[1][3], ah[1], bh[1][1], bh[1][3]);
        }
    }
}

// ---------------- 0) converts (hi only) ---------------------------------------
__global__ void convert_x_kernel(const float* __restrict__ src) {
    const int i4 = blockIdx.x * 256 + threadIdx.x;
    const size_t i = (size_t)i4 * 4;
    if (i + 3 < (size_t)BS_ * D_) {
        float4 v = *(const float4*)(src + i);
        *(__half2*)(g_Xhi + i) =
            __halves2half2(__float2half_rn(v.x), __float2half_rn(v.y));
        *(__half2*)(g_Xhi + i + 2) =
            __halves2half2(__float2half_rn(v.z), __float2half_rn(v.w));
    }
}

__global__ void convert_small_kernel(
    const float* __restrict__ w0, const float* __restrict__ w1,
    const float* __restrict__ w2, const float* __restrict__ w3,
    const float* __restrict__ r0, const float* __restrict__ r1)
{
    const int z = blockIdx.y;
    const float* src;
    __half* hi;
    int n;
    if (z < 4) {
        src = (z == 0) ? w0 : (z == 1) ? w1 : (z == 2) ? w2 : w3;
        hi = g_Whi[z]; n = D_ * D_;
    } else {
        src = (z == 4) ? r0 : r1;
        hi = g_Rhi[z - 4]; n = NREL * D_;
    }
    int i = blockIdx.x * 256 + threadIdx.x;
    if (i < n) hi[i] = __float2half_rn(src[i]);
}

// ---------------- 1) projections: ONE fused GEMM over W_cat[1024,256] --------
__global__ void __launch_bounds__(512, 2)
proj_kernel(const float* __restrict__ bq1, const float* __restrict__ bk1,
            const float* __restrict__ bq2, const float* __restrict__ bk2)
{
    const int mBase = blockIdx.y * 128;
    const int nBase = blockIdx.x * 128;      // 0..896, global W_cat row
    const int z = nBase >> 8;
    const int nLoc = nBase & 255;
    const float* bias = (z == 0) ? bq1 : (z == 1) ? bk1 : (z == 2) ? bq2 : bk2;
    const float scale = (z == 0 || z == 2) ? 0.0625f : 1.0f;

    float acc[2][4][4];
    gemm_core(g_Xhi, g_Whi[0], mBase, nBase, 1 << 30, acc);

    const int lane = threadIdx.x & 31, wid = threadIdx.x >> 5;
    const int mw = wid >> 2, nwq = wid & 3;

#pragma unroll
    for (int mt = 0; mt < 2; mt++) {
#pragma unroll
        for (int h = 0; h < 2; h++) {
            const int m = mBase + mw * 32 + mt * 16 + (lane >> 2) + 8 * h;
            __half* dhi = g_Phi[z] + (size_t)m * D_;
#pragma unroll
            for (int nt = 0; nt < 4; nt++) {
                const int col = nLoc + nwq * 32 + nt * 8 + (lane & 3) * 2;
                float y0 = (acc[mt][nt][h * 2 + 0] + bias[col + 0]) * scale;
                float y1 = (acc[mt][nt][h * 2 + 1] + bias[col + 1]) * scale;
                *(__half2*)(dhi + col) =
                    __halves2half2(__float2half_rn(y0), __float2half_rn(y1));
            }
        }
    }
}

// ---------------- 2) q_rel: cols 0..127 via GEMM ------------------------------
__global__ void __launch_bounds__(512, 2)
qr_kernel()
{
    const int head  = blockIdx.z;
    const int mBase = blockIdx.y * 128;

    float acc[2][4][4];
    gemm_core(g_Phi[head * 2], g_Rhi[head], mBase, 0, 128, acc);

    const int lane = threadIdx.x & 31, wid = threadIdx.x >> 5;
    const int mw = wid >> 2, nwq = wid & 3;

#pragma unroll
    for (int mt = 0; mt < 2; mt++) {
#pragma unroll
        for (int h = 0; h < 2; h++) {
            const int m = mBase + mw * 32 + mt * 16 + (lane >> 2) + 8 * h;
            float* dst = g_QR[head] + (size_t)m * QRS;
#pragma unroll
            for (int nt = 0; nt < 4; nt++) {
                const int col = nwq * 32 + nt * 8 + (lane & 3) * 2;
                *(float2*)(dst + col) =
                    make_float2(acc[mt][nt][h * 2 + 0], acc[mt][nt][h * 2 + 1]);
            }
        }
    }
}

// ---------------- 2b) q_rel column 128 via GEMV (f32 rel source) --------------
__global__ void __launch_bounds__(256)
qr_col_kernel(const float* __restrict__ rel1, const float* __restrict__ rel2)
{
    const int gw   = blockIdx.x * 8 + (threadIdx.x >> 5);  // 0..2047
    const int lane = threadIdx.x & 31;
    const int head = gw >> 10;
    const int row0 = (gw & 1023) * 16;

    const float* rel = (head == 0) ? rel1 : rel2;
    float rf[8];
    {
        const float* rrow = rel + (size_t)128 * D_ + lane * 8;
        float4 a = *(const float4*)(rrow + 0);
        float4 b = *(const float4*)(rrow + 4);
        rf[0] = a.x; rf[1] = a.y; rf[2] = a.z; rf[3] = a.w;
        rf[4] = b.x; rf[5] = b.y; rf[6] = b.z; rf[7] = b.w;
    }

    const __half* Qhi = g_Phi[head * 2];

    for (int r = 0; r < 16; r++) {
        const int row = row0 + r;
        uint4 vh = *(const uint4*)(Qhi + (size_t)row * D_ + lane * 8);
        const __half* ph = (const __half*)&vh;
        float s = 0.f;
#pragma unroll
        for (int j = 0; j < 8; j++)
            s += __half2float(ph[j]) * rf[j];
#pragma unroll
        for (int o = 16; o > 0; o >>= 1)
            s += __shfl_xor_sync(0xFFFFFFFF, s, o);
        if (lane == 0) g_QR[head][(size_t)row * QRS + 128] = s;
    }
}

// ---------------- 3) scores (fast/slow epilogue, streaming stores) ------------
__global__ void __launch_bounds__(512, 2)
scores_kernel(const int* __restrict__ mask, float* __restrict__ out)
{
    const int z    = blockIdx.z;
    const int head = z >> 3;
    const int b    = z & 7;
    const int qBase = blockIdx.y * 128;
    const int kBase = blockIdx.x * 128;

    const size_t po = (size_t)b * S_ * D_;
    float acc[2][4][4];
    gemm_core(g_Phi[head * 2 + 0] + po, g_Phi[head * 2 + 1] + po,
              qBase, kBase, 1 << 30, acc);

    const int lane = threadIdx.x & 31, wid = threadIdx.x >> 5;
    const int mw = wid >> 2, nwq = wid & 3;
    const int* mrow = mask + b * S_;

    const int dTile = kBase - qBase;
    const bool fastPath = (dTile >= 256) || (dTile <= -256);
    const int clampIdx = (dTile >= 256) ? 128 : 0;

#pragma unroll
    for (int mt = 0; mt < 2; mt++) {
#pragma unroll
        for (int h = 0; h < 2; h++) {
            const int qg = qBase + mw * 32 + mt * 16 + (lane >> 2) + 8 * h;
            const int mq = mrow[qg];
            const float* qr = g_QR[head] + ((size_t)b * S_ + qg) * QRS;
            float* orow = out + (((size_t)head * B_ + b) * S_ + qg) * S_;
            if (fastPath) {
                const float rc = qr[clampIdx];
#pragma unroll
                for (int nt = 0; nt < 4; nt++) {
                    const int kg = kBase + nwq * 32 + nt * 8 + (lane & 3) * 2;
                    float v0 = acc[mt][nt][h * 2 + 0] + rc;
                    float v1 = acc[mt][nt][h * 2 + 1] + rc;
                    if (mq == 0 || mrow[kg + 0] == 0) v0 = -1e18f;
                    if (mq == 0 || mrow[kg + 1] == 0) v1 = -1e18f;
                    stcs2(orow + kg, make_float2(v0, v1));
                }
            } else {
#pragma unroll
                for (int nt = 0; nt < 4; nt++) {
                    const int kg = kBase + nwq * 32 + nt * 8 + (lane & 3) * 2;
                    int d0 = kg - qg;
                    int d1 = d0 + 1;
                    d0 = (d0 < -64) ? -64 : ((d0 > 64) ? 64 : d0);
                    d1 = (d1 < -64) ? -64 : ((d1 > 64) ? 64 : d1);
                    float v0 = acc[mt][nt][h * 2 + 0] + qr[d0 + 64];
                    float v1 = acc[mt][nt][h * 2 + 1] + qr[d1 + 64];
                    if (mq == 0 || mrow[kg + 0] == 0) v0 = -1e18f;
                    if (mq == 0 || mrow[kg + 1] == 0) v1 = -1e18f;
                    stcs2(orow + kg, make_float2(v0, v1));
                }
            }
        }
    }
}

// ---------------- launch --------------------------------------------------------
extern "C" void kernel_launch(void* const* d_in, const int* in_sizes, int n_in,
                              void* d_out, int out_size)
{
    const float* repre = (const float*)d_in[0];
    const int*   mask  = (const int*)d_in[1];
    const float* wq1 = (const float*)d_in[2];
    const float* bq1 = (const float*)d_in[3];
    const float* wk1 = (const float*)d_in[4];
    const float* bk1 = (const float*)d_in[5];
    const float* rel1 = (const float*)d_in[6];
    const float* wq2 = (const float*)d_in[7];
    const float* bq2 = (const float*)d_in[8];
    const float* wk2 = (const float*)d_in[9];
    const float* bk2 = (const float*)d_in[10];
    const float* rel2 = (const float*)d_in[11];
    float* out = (float*)d_out;
    (void)in_sizes; (void)n_in; (void)out_size;

    cudaFuncSetAttribute(proj_kernel,
                         cudaFuncAttributeMaxDynamicSharedMemorySize, SMEM_DYN);
    cudaFuncSetAttribute(qr_kernel,
                         cudaFuncAttributeMaxDynamicSharedMemorySize, SMEM_DYN);
    cudaFuncSetAttribute(scores_kernel,
                         cudaFuncAttributeMaxDynamicSharedMemorySize, SMEM_DYN);

    const int NX4 = BS_ * D_ / 4;
    const int NW = D_ * D_;

    convert_x_kernel<<<(NX4 + 255) / 256, 256>>>(repre);
    convert_small_kernel<<<dim3((NW + 255) / 256, 6), 256>>>(
        wq1, wk1, wq2, wk2, rel1, rel2);

    proj_kernel<<<dim3(8, 128), 512, SMEM_DYN>>>(bq1, bk1, bq2, bk2);
    qr_kernel<<<dim3(1, 128, 2), 512, SMEM_DYN>>>();
    qr_col_kernel<<<256, 256>>>(rel1, rel2);
    scores_kernel<<<dim3(16, 16, 16), 512, SMEM_DYN>>>(mask, out);
}